// round 3
// baseline (speedup 1.0000x reference)
#include <cuda_runtime.h>
#include <math.h>

#define BATCH   2
#define IMH     256
#define IMW     256
#define C       192
#define HEADS   6
#define HD      32
#define HIDDEN  768
#define HW      (IMH*IMW)
#define M_TOK   (BATCH*HW)          // 131072
#define SCALE_Q 0.17677669529663687f

// ---------------- scratch buffers (device globals; no allocation) -----------
__device__ float g_xn  [M_TOK * C];         // LN output (reused for LN1 and LN2)
__device__ float g_q   [M_TOK * C];         // q projection
__device__ float g_kv  [M_TOK * (C/2)];     // kv projection (96 per token)
__device__ float g_aw  [M_TOK * C];         // attention output (natural token order)
__device__ float g_xmid[M_TOK * C];         // post-attention residual x
__device__ float g_h1  [(size_t)M_TOK * HIDDEN];  // FFN hidden
__device__ float g_h2  [(size_t)M_TOK * HIDDEN];  // h1 + gelu(dwconv)

// ---------------- LayerNorm: one warp per token ----------------------------
__global__ void ln_kernel(const float* __restrict__ x,
                          const float* __restrict__ g,
                          const float* __restrict__ b,
                          float* __restrict__ out) {
    int token = blockIdx.x * blockDim.y + threadIdx.y;
    int lane  = threadIdx.x;
    const float* row = x + (size_t)token * C;
    float v[6];
    float s = 0.f;
#pragma unroll
    for (int i = 0; i < 6; i++) { v[i] = row[lane + 32*i]; s += v[i]; }
#pragma unroll
    for (int o = 16; o > 0; o >>= 1) s += __shfl_xor_sync(0xffffffffu, s, o);
    float mean = s * (1.0f / C);
    float s2 = 0.f;
#pragma unroll
    for (int i = 0; i < 6; i++) { float d = v[i] - mean; s2 += d * d; }
#pragma unroll
    for (int o = 16; o > 0; o >>= 1) s2 += __shfl_xor_sync(0xffffffffu, s2, o);
    float rstd = rsqrtf(s2 * (1.0f / C) + 1e-5f);
    float* orow = out + (size_t)token * C;
#pragma unroll
    for (int i = 0; i < 6; i++) {
        int cc = lane + 32*i;
        orow[cc] = (v[i] - mean) * rstd * g[cc] + b[cc];
    }
}

// ---------------- register-tiled fp32 GEMM ----------------------------------
// OUT[M,N] = epi( A[M,K] @ W[K,N] + bias[N] )   (all row-major)
// EPI: 0 = bias only   1 = bias + exact gelu   2 = bias + residual
template<int BN, int TN, int EPI>
__global__ void __launch_bounds__(128)
gemm_kernel(const float* __restrict__ A, const float* __restrict__ Wt,
            const float* __restrict__ bias, const float* __restrict__ res,
            float* __restrict__ out, int M, int N, int K) {
    constexpr int BM = 128, BK = 16, TM = 8;
    constexpr int TXN = BN / TN;            // threads along N (=8)
    __shared__ float As[BK][BM];
    __shared__ float Ws[BK][BN];

    int m0 = blockIdx.x * BM;
    int n0 = blockIdx.y * BN;
    int tid = threadIdx.x;
    int tx = tid % TXN;
    int ty = tid / TXN;                     // 0..15

    float acc[TM][TN];
#pragma unroll
    for (int i = 0; i < TM; i++)
#pragma unroll
        for (int j = 0; j < TN; j++) acc[i][j] = 0.f;

    const float* Arow = A + (size_t)(m0 + tid) * K;

    for (int k0 = 0; k0 < K; k0 += BK) {
        // A tile: 128 rows x 16 k, stored transposed As[k][m]
#pragma unroll
        for (int q = 0; q < 4; q++) {
            float4 t4 = *(const float4*)(Arow + k0 + q*4);
            As[q*4+0][tid] = t4.x; As[q*4+1][tid] = t4.y;
            As[q*4+2][tid] = t4.z; As[q*4+3][tid] = t4.w;
        }
        // W tile: BK x BN
        constexpr int NF4 = BK * BN / 4;
        for (int f = tid; f < NF4; f += 128) {
            int row = f / (BN/4);
            int col = (f % (BN/4)) * 4;
            *(float4*)&Ws[row][col] =
                *(const float4*)(Wt + (size_t)(k0 + row) * N + n0 + col);
        }
        __syncthreads();
#pragma unroll
        for (int kk = 0; kk < BK; kk++) {
            float a[TM], bf[TN];
            *(float4*)&a[0] = *(const float4*)&As[kk][ty*TM];
            *(float4*)&a[4] = *(const float4*)&As[kk][ty*TM + 4];
#pragma unroll
            for (int j = 0; j < TN; j += 4)
                *(float4*)&bf[j] = *(const float4*)&Ws[kk][tx*TN + j];
#pragma unroll
            for (int i = 0; i < TM; i++)
#pragma unroll
                for (int j = 0; j < TN; j++) acc[i][j] += a[i] * bf[j];
        }
        __syncthreads();
    }

    // epilogue
    float bv[TN];
#pragma unroll
    for (int j = 0; j < TN; j++) bv[j] = bias[n0 + tx*TN + j];
#pragma unroll
    for (int i = 0; i < TM; i++) {
        int m = m0 + ty*TM + i;
        float* orow = out + (size_t)m * N + n0 + tx*TN;
        const float* rrow = (EPI == 2) ? (res + (size_t)m * N + n0 + tx*TN) : nullptr;
        float v[TN];
#pragma unroll
        for (int j = 0; j < TN; j++) {
            float t = acc[i][j] + bv[j];
            if (EPI == 1) t = t * normcdff(t);
            if (EPI == 2) t += rrow[j];
            v[j] = t;
        }
#pragma unroll
        for (int j = 0; j < TN; j += 4)
            *(float4*)(orow + j) = *(float4*)&v[j];
    }
}

// ---------------- fused window attention ------------------------------------
// one block per 8x8 window; q scaled here; kv permuted to k/v [16][192];
// relative-position bias computed from window coords; softmax over 16.
__global__ void __launch_bounds__(384)
attn_kernel(const float* __restrict__ q, const float* __restrict__ kv,
            const float* __restrict__ table, float* __restrict__ aw) {
    extern __shared__ float smem[];
    float* ks  = smem;                 // [16][192]
    float* vs  = ks + 16*192;          // [16][192]
    float* aws = vs + 16*192;          // [64][192]
    float* tb  = aws + 64*192;         // [49*6]

    int w  = blockIdx.x;
    int bb = w >> 10;
    int wi = w & 1023;
    int wy = wi >> 5, wx = wi & 31;
    size_t base = (size_t)bb * HW + (size_t)(wy*8) * IMW + wx*8;
    int tid = threadIdx.x;

    for (int e = tid; e < 49*HEADS; e += 384) tb[e] = table[e];

    // gather + permute kv -> k [16][192], v [16][192]
    for (int e = tid; e < 64*48; e += 384) {
        int s  = e / 48, cc = e - s*48;
        int r  = s >> 3, c = s & 7;
        int p  = (r >> 1) * 4 + (c >> 1);
        int f  = (r & 1) * 96 + (c & 1) * 48 + cc;
        const float* src = kv + (base + (size_t)r * IMW + c) * (C/2);
        ks[p*192 + f] = src[cc];
        vs[p*192 + f] = src[48 + cc];
    }
    __syncthreads();

    int h  = tid / 64;                 // 0..5
    int qt = tid & 63;                 // 0..63
    int r  = qt >> 3, c = qt & 7;
    int ph = r >> 1, pw = c >> 1;

    const float* qrow = q + (base + (size_t)r * IMW + c) * C + h*HD;
    float qr[HD];
#pragma unroll
    for (int d = 0; d < HD; d += 4) {
        float4 t4 = *(const float4*)(qrow + d);
        qr[d+0] = t4.x * SCALE_Q; qr[d+1] = t4.y * SCALE_Q;
        qr[d+2] = t4.z * SCALE_Q; qr[d+3] = t4.w * SCALE_Q;
    }

    float s[16], m = -1e30f;
#pragma unroll
    for (int kt = 0; kt < 16; kt++) {
        int kh = kt >> 2, kw = kt & 3;
        float acc = tb[((ph - kh + 3) * 7 + (pw - kw + 3)) * HEADS + h];
        const float* kr = &ks[kt*192 + h*HD];
#pragma unroll
        for (int d = 0; d < HD; d++) acc += qr[d] * kr[d];
        s[kt] = acc;
        m = fmaxf(m, acc);
    }
    float sum = 0.f;
#pragma unroll
    for (int kt = 0; kt < 16; kt++) { s[kt] = __expf(s[kt] - m); sum += s[kt]; }
    float inv = 1.0f / sum;

#pragma unroll
    for (int d = 0; d < HD; d++) {
        float o = 0.f;
#pragma unroll
        for (int kt = 0; kt < 16; kt++) o += s[kt] * vs[kt*192 + h*HD + d];
        aws[qt*192 + h*HD + d] = o * inv;
    }
    __syncthreads();

    // coalesced writeback in natural token order
    for (int e = tid; e < 64*192; e += 384) {
        int t = e / 192, f = e - t*192;
        int rr = t >> 3, cc2 = t & 7;
        aw[(base + (size_t)rr * IMW + cc2) * C + f] = aws[e];
    }
}

// ---------------- depthwise 5x5 conv + gelu + add ---------------------------
// h2 = h1 + gelu(dwconv5x5(h1) + dwb)
__global__ void __launch_bounds__(256)
dwconv_kernel(const float* __restrict__ h1, const float* __restrict__ dwk,
              const float* __restrict__ dwb, float* __restrict__ out) {
    constexpr int TS = 16, CCH = 32, TT = TS + 4;
    extern __shared__ float smem[];
    float* tile = smem;                 // [20][20][32]
    float* wk   = tile + TT*TT*CCH;     // [32][25]
    float* bk   = wk + CCH*25;          // [32]

    int bz = blockIdx.z;
    int bb = bz / (HIDDEN / CCH);
    int c0 = (bz % (HIDDEN / CCH)) * CCH;
    int x0 = blockIdx.x * TS, y0 = blockIdx.y * TS;
    int tid = threadIdx.x;

    for (int e = tid; e < CCH*25; e += 256) {
        int cc = e / 25, t = e - cc*25;
        wk[cc*25 + t] = dwk[(c0 + cc) * 25 + t];
    }
    if (tid < CCH) bk[tid] = dwb[c0 + tid];

    // load (16+4)^2 x 32ch halo tile (zeros outside)
    for (int e = tid; e < TT*TT*(CCH/4); e += 256) {
        int pos = e / (CCH/4);
        int qv  = e - pos*(CCH/4);
        int py = pos / TT, px = pos - py*TT;
        int gy = y0 + py - 2, gx = x0 + px - 2;
        float4 t4 = make_float4(0.f, 0.f, 0.f, 0.f);
        if (gy >= 0 && gy < IMH && gx >= 0 && gx < IMW)
            t4 = *(const float4*)(h1 + ((size_t)bb*HW + (size_t)gy*IMW + gx)*HIDDEN + c0 + qv*4);
        *(float4*)&tile[(py*TT + px)*CCH + qv*4] = t4;
    }
    __syncthreads();

    int cc = tid & (CCH-1);
    int sq = tid >> 5;                  // 0..7
    const float* wr = &wk[cc*25];
    float bia = bk[cc];
    for (int i = 0; i < 32; i++) {
        int sp = sq * 32 + i;
        int y = sp >> 4, x = sp & 15;
        float acc = 0.f;
#pragma unroll
        for (int dy = 0; dy < 5; dy++)
#pragma unroll
            for (int dx = 0; dx < 5; dx++)
                acc += tile[((y+dy)*TT + (x+dx))*CCH + cc] * wr[dy*5 + dx];
        float gv = acc + bia;
        gv = gv * normcdff(gv);
        size_t o = ((size_t)bb*HW + (size_t)(y0+y)*IMW + (x0+x))*HIDDEN + c0 + cc;
        out[o] = h1[o] + gv;
    }
}

// ---------------- launch ----------------------------------------------------
extern "C" void kernel_launch(void* const* d_in, const int* in_sizes, int n_in,
                              void* d_out, int out_size) {
    const float* x     = (const float*)d_in[0];
    const float* g1    = (const float*)d_in[1];
    const float* be1   = (const float*)d_in[2];
    const float* wq    = (const float*)d_in[3];
    const float* bq    = (const float*)d_in[4];
    const float* wkv   = (const float*)d_in[5];
    const float* bkv   = (const float*)d_in[6];
    const float* table = (const float*)d_in[7];
    const float* wproj = (const float*)d_in[8];
    const float* bproj = (const float*)d_in[9];
    const float* g2    = (const float*)d_in[10];
    const float* be2   = (const float*)d_in[11];
    const float* w1f   = (const float*)d_in[12];
    const float* b1f   = (const float*)d_in[13];
    const float* dwk   = (const float*)d_in[14];
    const float* dwb   = (const float*)d_in[15];
    const float* w2f   = (const float*)d_in[16];
    const float* b2f   = (const float*)d_in[17];
    float* out = (float*)d_out;

    void *pxn, *pq, *pkv, *paw, *pxmid, *ph1, *ph2;
    cudaGetSymbolAddress(&pxn,   g_xn);
    cudaGetSymbolAddress(&pq,    g_q);
    cudaGetSymbolAddress(&pkv,   g_kv);
    cudaGetSymbolAddress(&paw,   g_aw);
    cudaGetSymbolAddress(&pxmid, g_xmid);
    cudaGetSymbolAddress(&ph1,   g_h1);
    cudaGetSymbolAddress(&ph2,   g_h2);
    float* xn   = (float*)pxn;
    float* qb   = (float*)pq;
    float* kvb  = (float*)pkv;
    float* awb  = (float*)paw;
    float* xmid = (float*)pxmid;
    float* h1   = (float*)ph1;
    float* h2   = (float*)ph2;

    const int ASMEM = (16*192*2 + 64*192 + 49*HEADS) * 4;       // 74904
    const int CSMEM = (20*20*32 + 32*25 + 32) * 4;              // 54528
    cudaFuncSetAttribute(attn_kernel,   cudaFuncAttributeMaxDynamicSharedMemorySize, ASMEM);
    cudaFuncSetAttribute(dwconv_kernel, cudaFuncAttributeMaxDynamicSharedMemorySize, CSMEM);

    dim3 lnb(32, 8);

    // 1) LN1
    ln_kernel<<<M_TOK/8, lnb>>>(x, g1, be1, xn);
    // 2) q = xn @ wq + bq
    gemm_kernel<64, 8, 0><<<dim3(M_TOK/128, 3), 128>>>(xn, wq, bq, nullptr, qb, M_TOK, 192, 192);
    // 3) kv = xn @ wkv + bkv
    gemm_kernel<32, 4, 0><<<dim3(M_TOK/128, 3), 128>>>(xn, wkv, bkv, nullptr, kvb, M_TOK, 96, 192);
    // 4) window attention -> aw (natural token order)
    attn_kernel<<<2048, 384, ASMEM>>>(qb, kvb, table, awb);
    // 5) xmid = x + aw @ wproj + bproj
    gemm_kernel<64, 8, 2><<<dim3(M_TOK/128, 3), 128>>>(awb, wproj, bproj, x, xmid, M_TOK, 192, 192);
    // 6) LN2
    ln_kernel<<<M_TOK/8, lnb>>>(xmid, g2, be2, xn);
    // 7) h1 = gelu(xn @ w1f + b1f)
    gemm_kernel<64, 8, 1><<<dim3(M_TOK/128, 12), 128>>>(xn, w1f, b1f, nullptr, h1, M_TOK, 768, 192);
    // 8) h2 = h1 + gelu(dwconv(h1) + dwb)
    dwconv_kernel<<<dim3(IMW/16, IMH/16, BATCH*(HIDDEN/32)), 256, CSMEM>>>(h1, dwk, dwb, h2);
    // 9) out = xmid + h2 @ w2f + b2f
    gemm_kernel<64, 8, 2><<<dim3(M_TOK/128, 3), 128>>>(h2, w2f, b2f, xmid, out, M_TOK, 192, 768);
}

// round 4
// speedup vs baseline: 1.5333x; 1.5333x over previous
#include <cuda_runtime.h>
#include <math.h>
#include <stdint.h>

#define BATCH   2
#define IMH     256
#define IMW     256
#define C       192
#define HEADS   6
#define HD      32
#define HIDDEN  768
#define HW      (IMH*IMW)
#define M_TOK   (BATCH*HW)          // 131072
#define SCALE_Q 0.17677669529663687f

// ---------------- scratch buffers (device globals; no allocation) -----------
__device__ float g_xn  [M_TOK * C];
__device__ float g_q   [M_TOK * C];
__device__ float g_kv  [M_TOK * (C/2)];
__device__ float g_aw  [M_TOK * C];
__device__ float g_xmid[M_TOK * C];
__device__ float g_h1  [(size_t)M_TOK * HIDDEN];
__device__ float g_h2  [(size_t)M_TOK * HIDDEN];

// ---------------- LayerNorm: one warp per token ----------------------------
__global__ void ln_kernel(const float* __restrict__ x,
                          const float* __restrict__ g,
                          const float* __restrict__ b,
                          float* __restrict__ out) {
    int token = blockIdx.x * blockDim.y + threadIdx.y;
    int lane  = threadIdx.x;
    const float* row = x + (size_t)token * C;
    float v[6];
    float s = 0.f;
#pragma unroll
    for (int i = 0; i < 6; i++) { v[i] = row[lane + 32*i]; s += v[i]; }
#pragma unroll
    for (int o = 16; o > 0; o >>= 1) s += __shfl_xor_sync(0xffffffffu, s, o);
    float mean = s * (1.0f / C);
    float s2 = 0.f;
#pragma unroll
    for (int i = 0; i < 6; i++) { float d = v[i] - mean; s2 += d * d; }
#pragma unroll
    for (int o = 16; o > 0; o >>= 1) s2 += __shfl_xor_sync(0xffffffffu, s2, o);
    float rstd = rsqrtf(s2 * (1.0f / C) + 1e-5f);
    float* orow = out + (size_t)token * C;
#pragma unroll
    for (int i = 0; i < 6; i++) {
        int cc = lane + 32*i;
        orow[cc] = (v[i] - mean) * rstd * g[cc] + b[cc];
    }
}

// ---------------- TF32 tensor-core GEMM -------------------------------------
// OUT[M,N] = epi( A[M,K] @ W[K,N] + bias[N] )   (all row-major)
// EPI: 0 = bias only   1 = bias + exact gelu   2 = bias + residual
// BM=128, BN=96, BK=32, 256 threads = 8 warps arranged 4(m) x 2(n),
// warp tile 32x48 = 2 m-tiles x 6 n-tiles of m16n8k8.
// blockIdx.x = n-block (fast, so concurrent blocks share A via L2),
// blockIdx.y = m-block.

__device__ __forceinline__ uint32_t tf32r(float x) {
    uint32_t u;
    asm("cvt.rna.tf32.f32 %0, %1;" : "=r"(u) : "f"(x));
    return u;
}

__device__ __forceinline__ void mma_tf32(float* d, const uint32_t* a,
                                         uint32_t b0, uint32_t b1) {
    asm volatile(
        "mma.sync.aligned.m16n8k8.row.col.f32.tf32.tf32.f32 "
        "{%0,%1,%2,%3},{%4,%5,%6,%7},{%8,%9},{%0,%1,%2,%3};"
        : "+f"(d[0]), "+f"(d[1]), "+f"(d[2]), "+f"(d[3])
        : "r"(a[0]), "r"(a[1]), "r"(a[2]), "r"(a[3]), "r"(b0), "r"(b1));
}

// smem is indexed in float2 (k, k+4) pairs; col c = (k>>3)*4 + (k&3), c in [0,16)
__device__ __forceinline__ int sw_idx(int row, int c) {
    return row * 16 + (c ^ ((row & 7) << 1));
}

template<int EPI>
__global__ void __launch_bounds__(256, 1)
gemm_tf32(const float* __restrict__ A, const float* __restrict__ W,
          const float* __restrict__ bias, const float* __restrict__ res,
          float* __restrict__ out, int M, int N, int K) {
    extern __shared__ uint2 smu[];   // [A0:2048][A1:2048][B0:1536][B1:1536]

    const int tid  = threadIdx.x;
    const int wid  = tid >> 5, lane = tid & 31;
    const int wm   = wid >> 1, wn = wid & 1;
    const int gid  = lane >> 2, tig = lane & 3;
    const int n0   = blockIdx.x * 96;
    const int m0   = blockIdx.y * 128;

    // staging assignments
    const int arow  = tid >> 1;           // 0..127
    const int ahalf = tid & 1;            // k-half (16 floats)
    const float* gA = A + (size_t)(m0 + arow) * K + ahalf * 16;
    const int  bn    = tid >> 1;          // 0..95 for tid<192
    const int  bhalf = tid & 1;
    const bool bact  = (tid < 192);
    const float* gB  = W + n0 + bn;

    float acc[2][6][4];
#pragma unroll
    for (int mt = 0; mt < 2; mt++)
#pragma unroll
        for (int nt = 0; nt < 6; nt++)
#pragma unroll
            for (int r = 0; r < 4; r++) acc[mt][nt][r] = 0.f;

    float ar[16], br[16];
    const int nk = K / 32;

    // ---- prologue: stage k-tile 0 -> buf 0
#pragma unroll
    for (int q = 0; q < 4; q++)
        *(float4*)&ar[q * 4] = *(const float4*)(gA + q * 4);
    if (bact) {
#pragma unroll
        for (int kk = 0; kk < 16; kk++)
            br[kk] = gB[(size_t)(bhalf * 16 + kk) * N];
    }
    {
        uint2* Ab = smu;
        uint2* Bb = smu + 4096;
#pragma unroll
        for (int j = 0; j < 8; j++) {
            int c  = ahalf * 8 + j;
            int lo = (j >> 2) * 8 + (j & 3);
            Ab[sw_idx(arow, c)] = make_uint2(tf32r(ar[lo]), tf32r(ar[lo + 4]));
        }
        if (bact) {
#pragma unroll
            for (int j = 0; j < 8; j++) {
                int c  = bhalf * 8 + j;
                int lo = (j >> 2) * 8 + (j & 3);
                Bb[sw_idx(bn, c)] = make_uint2(tf32r(br[lo]), tf32r(br[lo + 4]));
            }
        }
    }
    __syncthreads();

    for (int kt = 0; kt < nk; kt++) {
        // prefetch next k-tile into registers
        if (kt + 1 < nk) {
            const float* pA = gA + (kt + 1) * 32;
#pragma unroll
            for (int q = 0; q < 4; q++)
                *(float4*)&ar[q * 4] = *(const float4*)(pA + q * 4);
            if (bact) {
                const float* pB = gB + (size_t)(kt + 1) * 32 * N;
#pragma unroll
                for (int kk = 0; kk < 16; kk++)
                    br[kk] = pB[(size_t)(bhalf * 16 + kk) * N];
            }
        }

        // compute on buffer kt&1
        const uint2* Ab = smu + (kt & 1) * 2048;
        const uint2* Bb = smu + 4096 + (kt & 1) * 1536;
#pragma unroll
        for (int s = 0; s < 4; s++) {
            uint32_t af[2][4];
#pragma unroll
            for (int mt = 0; mt < 2; mt++) {
                int r0 = wm * 32 + mt * 16 + gid;
                uint2 p0 = Ab[sw_idx(r0,     s * 4 + tig)];
                uint2 p1 = Ab[sw_idx(r0 + 8, s * 4 + tig)];
                af[mt][0] = p0.x; af[mt][1] = p1.x;
                af[mt][2] = p0.y; af[mt][3] = p1.y;
            }
#pragma unroll
            for (int nt = 0; nt < 6; nt++) {
                int nn  = wn * 48 + nt * 8 + gid;
                uint2 bp = Bb[sw_idx(nn, s * 4 + tig)];
#pragma unroll
                for (int mt = 0; mt < 2; mt++)
                    mma_tf32(acc[mt][nt], af[mt], bp.x, bp.y);
            }
        }

        // store staged tile to other buffer
        if (kt + 1 < nk) {
            uint2* Aw = smu + ((kt + 1) & 1) * 2048;
            uint2* Bw = smu + 4096 + ((kt + 1) & 1) * 1536;
#pragma unroll
            for (int j = 0; j < 8; j++) {
                int c  = ahalf * 8 + j;
                int lo = (j >> 2) * 8 + (j & 3);
                Aw[sw_idx(arow, c)] = make_uint2(tf32r(ar[lo]), tf32r(ar[lo + 4]));
            }
            if (bact) {
#pragma unroll
                for (int j = 0; j < 8; j++) {
                    int c  = bhalf * 8 + j;
                    int lo = (j >> 2) * 8 + (j & 3);
                    Bw[sw_idx(bn, c)] = make_uint2(tf32r(br[lo]), tf32r(br[lo + 4]));
                }
            }
            __syncthreads();
        }
    }

    // ---- epilogue
#pragma unroll
    for (int nt = 0; nt < 6; nt++) {
        int cb = n0 + wn * 48 + nt * 8 + 2 * tig;
        float b0 = bias[cb], b1 = bias[cb + 1];
#pragma unroll
        for (int mt = 0; mt < 2; mt++) {
            int r0 = m0 + wm * 32 + mt * 16 + gid;
#pragma unroll
            for (int hh = 0; hh < 2; hh++) {
                int r = r0 + hh * 8;
                float v0 = acc[mt][nt][hh * 2 + 0] + b0;
                float v1 = acc[mt][nt][hh * 2 + 1] + b1;
                if (EPI == 1) { v0 = v0 * normcdff(v0); v1 = v1 * normcdff(v1); }
                if (EPI == 2) {
                    const float* rr = res + (size_t)r * N + cb;
                    v0 += rr[0]; v1 += rr[1];
                }
                *(float2*)(out + (size_t)r * N + cb) = make_float2(v0, v1);
            }
        }
    }
}

// ---------------- fused window attention ------------------------------------
__global__ void __launch_bounds__(384)
attn_kernel(const float* __restrict__ q, const float* __restrict__ kv,
            const float* __restrict__ table, float* __restrict__ aw) {
    extern __shared__ float smem[];
    float* ks  = smem;                 // [16][192]
    float* vs  = ks + 16*192;          // [16][192]
    float* aws = vs + 16*192;          // [64][192]
    float* tb  = aws + 64*192;         // [49*6]

    int w  = blockIdx.x;
    int bb = w >> 10;
    int wi = w & 1023;
    int wy = wi >> 5, wx = wi & 31;
    size_t base = (size_t)bb * HW + (size_t)(wy*8) * IMW + wx*8;
    int tid = threadIdx.x;

    for (int e = tid; e < 49*HEADS; e += 384) tb[e] = table[e];

    for (int e = tid; e < 64*48; e += 384) {
        int s  = e / 48, cc = e - s*48;
        int r  = s >> 3, c = s & 7;
        int p  = (r >> 1) * 4 + (c >> 1);
        int f  = (r & 1) * 96 + (c & 1) * 48 + cc;
        const float* src = kv + (base + (size_t)r * IMW + c) * (C/2);
        ks[p*192 + f] = src[cc];
        vs[p*192 + f] = src[48 + cc];
    }
    __syncthreads();

    int h  = tid / 64;
    int qt = tid & 63;
    int r  = qt >> 3, c = qt & 7;
    int ph = r >> 1, pw = c >> 1;

    const float* qrow = q + (base + (size_t)r * IMW + c) * C + h*HD;
    float qr[HD];
#pragma unroll
    for (int d = 0; d < HD; d += 4) {
        float4 t4 = *(const float4*)(qrow + d);
        qr[d+0] = t4.x * SCALE_Q; qr[d+1] = t4.y * SCALE_Q;
        qr[d+2] = t4.z * SCALE_Q; qr[d+3] = t4.w * SCALE_Q;
    }

    float s[16], m = -1e30f;
#pragma unroll
    for (int kt = 0; kt < 16; kt++) {
        int kh = kt >> 2, kw = kt & 3;
        float acc = tb[((ph - kh + 3) * 7 + (pw - kw + 3)) * HEADS + h];
        const float* kr = &ks[kt*192 + h*HD];
#pragma unroll
        for (int d = 0; d < HD; d++) acc += qr[d] * kr[d];
        s[kt] = acc;
        m = fmaxf(m, acc);
    }
    float sum = 0.f;
#pragma unroll
    for (int kt = 0; kt < 16; kt++) { s[kt] = __expf(s[kt] - m); sum += s[kt]; }
    float inv = 1.0f / sum;

#pragma unroll
    for (int d = 0; d < HD; d++) {
        float o = 0.f;
#pragma unroll
        for (int kt = 0; kt < 16; kt++) o += s[kt] * vs[kt*192 + h*HD + d];
        aws[qt*192 + h*HD + d] = o * inv;
    }
    __syncthreads();

    for (int e = tid; e < 64*192; e += 384) {
        int t = e / 192, f = e - t*192;
        int rr = t >> 3, cc2 = t & 7;
        aw[(base + (size_t)rr * IMW + cc2) * C + f] = aws[e];
    }
}

// ---------------- depthwise 5x5 conv + gelu + add ---------------------------
__global__ void __launch_bounds__(256)
dwconv_kernel(const float* __restrict__ h1, const float* __restrict__ dwk,
              const float* __restrict__ dwb, float* __restrict__ out) {
    constexpr int TS = 16, CCH = 32, TT = TS + 4;
    extern __shared__ float smem[];
    float* tile = smem;
    float* wk   = tile + TT*TT*CCH;
    float* bk   = wk + CCH*25;

    int bz = blockIdx.z;
    int bb = bz / (HIDDEN / CCH);
    int c0 = (bz % (HIDDEN / CCH)) * CCH;
    int x0 = blockIdx.x * TS, y0 = blockIdx.y * TS;
    int tid = threadIdx.x;

    for (int e = tid; e < CCH*25; e += 256) {
        int cc = e / 25, t = e - cc*25;
        wk[cc*25 + t] = dwk[(c0 + cc) * 25 + t];
    }
    if (tid < CCH) bk[tid] = dwb[c0 + tid];

    for (int e = tid; e < TT*TT*(CCH/4); e += 256) {
        int pos = e / (CCH/4);
        int qv  = e - pos*(CCH/4);
        int py = pos / TT, px = pos - py*TT;
        int gy = y0 + py - 2, gx = x0 + px - 2;
        float4 t4 = make_float4(0.f, 0.f, 0.f, 0.f);
        if (gy >= 0 && gy < IMH && gx >= 0 && gx < IMW)
            t4 = *(const float4*)(h1 + ((size_t)bb*HW + (size_t)gy*IMW + gx)*HIDDEN + c0 + qv*4);
        *(float4*)&tile[(py*TT + px)*CCH + qv*4] = t4;
    }
    __syncthreads();

    int cc = tid & (CCH-1);
    int sq = tid >> 5;
    const float* wr = &wk[cc*25];
    float bia = bk[cc];
    for (int i = 0; i < 32; i++) {
        int sp = sq * 32 + i;
        int y = sp >> 4, x = sp & 15;
        float acc = 0.f;
#pragma unroll
        for (int dy = 0; dy < 5; dy++)
#pragma unroll
            for (int dx = 0; dx < 5; dx++)
                acc += tile[((y+dy)*TT + (x+dx))*CCH + cc] * wr[dy*5 + dx];
        float gv = acc + bia;
        gv = gv * normcdff(gv);
        size_t o = ((size_t)bb*HW + (size_t)(y0+y)*IMW + (x0+x))*HIDDEN + c0 + cc;
        out[o] = h1[o] + gv;
    }
}

// ---------------- launch ----------------------------------------------------
extern "C" void kernel_launch(void* const* d_in, const int* in_sizes, int n_in,
                              void* d_out, int out_size) {
    const float* x     = (const float*)d_in[0];
    const float* g1    = (const float*)d_in[1];
    const float* be1   = (const float*)d_in[2];
    const float* wq    = (const float*)d_in[3];
    const float* bq    = (const float*)d_in[4];
    const float* wkv   = (const float*)d_in[5];
    const float* bkv   = (const float*)d_in[6];
    const float* table = (const float*)d_in[7];
    const float* wproj = (const float*)d_in[8];
    const float* bproj = (const float*)d_in[9];
    const float* g2    = (const float*)d_in[10];
    const float* be2   = (const float*)d_in[11];
    const float* w1f   = (const float*)d_in[12];
    const float* b1f   = (const float*)d_in[13];
    const float* dwk   = (const float*)d_in[14];
    const float* dwb   = (const float*)d_in[15];
    const float* w2f   = (const float*)d_in[16];
    const float* b2f   = (const float*)d_in[17];
    float* out = (float*)d_out;

    void *pxn, *pq, *pkv, *paw, *pxmid, *ph1, *ph2;
    cudaGetSymbolAddress(&pxn,   g_xn);
    cudaGetSymbolAddress(&pq,    g_q);
    cudaGetSymbolAddress(&pkv,   g_kv);
    cudaGetSymbolAddress(&paw,   g_aw);
    cudaGetSymbolAddress(&pxmid, g_xmid);
    cudaGetSymbolAddress(&ph1,   g_h1);
    cudaGetSymbolAddress(&ph2,   g_h2);
    float* xn   = (float*)pxn;
    float* qb   = (float*)pq;
    float* kvb  = (float*)pkv;
    float* awb  = (float*)paw;
    float* xmid = (float*)pxmid;
    float* h1   = (float*)ph1;
    float* h2   = (float*)ph2;

    const int ASMEM = (16*192*2 + 64*192 + 49*HEADS) * 4;
    const int CSMEM = (20*20*32 + 32*25 + 32) * 4;
    const int GSMEM = (2*2048 + 2*1536) * 8;              // 57344
    cudaFuncSetAttribute(attn_kernel,   cudaFuncAttributeMaxDynamicSharedMemorySize, ASMEM);
    cudaFuncSetAttribute(dwconv_kernel, cudaFuncAttributeMaxDynamicSharedMemorySize, CSMEM);
    cudaFuncSetAttribute(gemm_tf32<0>,  cudaFuncAttributeMaxDynamicSharedMemorySize, GSMEM);
    cudaFuncSetAttribute(gemm_tf32<1>,  cudaFuncAttributeMaxDynamicSharedMemorySize, GSMEM);
    cudaFuncSetAttribute(gemm_tf32<2>,  cudaFuncAttributeMaxDynamicSharedMemorySize, GSMEM);

    dim3 lnb(32, 8);
    const int MB = M_TOK / 128;   // 1024 m-blocks

    // 1) LN1
    ln_kernel<<<M_TOK/8, lnb>>>(x, g1, be1, xn);
    // 2) q = xn @ wq + bq          (N=192 -> 2 n-blocks)
    gemm_tf32<0><<<dim3(2, MB), 256, GSMEM>>>(xn, wq, bq, nullptr, qb, M_TOK, 192, 192);
    // 3) kv = xn @ wkv + bkv       (N=96 -> 1 n-block)
    gemm_tf32<0><<<dim3(1, MB), 256, GSMEM>>>(xn, wkv, bkv, nullptr, kvb, M_TOK, 96, 192);
    // 4) window attention
    attn_kernel<<<2048, 384, ASMEM>>>(qb, kvb, table, awb);
    // 5) xmid = x + aw @ wproj + bproj
    gemm_tf32<2><<<dim3(2, MB), 256, GSMEM>>>(awb, wproj, bproj, x, xmid, M_TOK, 192, 192);
    // 6) LN2
    ln_kernel<<<M_TOK/8, lnb>>>(xmid, g2, be2, xn);
    // 7) h1 = gelu(xn @ w1f + b1f) (N=768 -> 8 n-blocks)
    gemm_tf32<1><<<dim3(8, MB), 256, GSMEM>>>(xn, w1f, b1f, nullptr, h1, M_TOK, 768, 192);
    // 8) h2 = h1 + gelu(dwconv(h1) + dwb)
    dwconv_kernel<<<dim3(IMW/16, IMH/16, BATCH*(HIDDEN/32)), 256, CSMEM>>>(h1, dwk, dwb, h2);
    // 9) out = xmid + h2 @ w2f + b2f   (K=768)
    gemm_tf32<2><<<dim3(2, MB), 256, GSMEM>>>(h2, w2f, b2f, xmid, out, M_TOK, 192, 768);
}

// round 5
// speedup vs baseline: 2.6899x; 1.7544x over previous
#include <cuda_runtime.h>
#include <cuda_bf16.h>
#include <math.h>
#include <stdint.h>

#define BATCH   2
#define IMH     256
#define IMW     256
#define C       192
#define HEADS   6
#define HD      32
#define HIDDEN  768
#define HW      (IMH*IMW)
#define M_TOK   (BATCH*HW)          // 131072
#define SCALE_Q 0.17677669529663687f

typedef __nv_bfloat16  bf16;
typedef __nv_bfloat162 bf162;

// ---------------- scratch buffers (device globals; no allocation) -----------
__device__ bf16  g_xn  [M_TOK * C];               // LN output (bf16)
__device__ bf16  g_q   [M_TOK * C];
__device__ bf16  g_kv  [M_TOK * (C/2)];
__device__ bf16  g_aw  [M_TOK * C];
__device__ float g_xmid[M_TOK * C];               // residual spine stays fp32
__device__ bf16  g_h1  [(size_t)M_TOK * HIDDEN];
__device__ bf16  g_h2  [(size_t)M_TOK * HIDDEN];

__device__ __forceinline__ uint32_t bf2(float lo, float hi) {
    bf162 h = __floats2bfloat162_rn(lo, hi);
    return *(uint32_t*)&h;
}

// ---------------- LayerNorm: one warp per token, bf16 out -------------------
__global__ void ln_kernel(const float* __restrict__ x,
                          const float* __restrict__ g,
                          const float* __restrict__ b,
                          bf16* __restrict__ out) {
    int token = blockIdx.x * blockDim.y + threadIdx.y;
    int lane  = threadIdx.x;
    const float* row = x + (size_t)token * C;
    float v[6];
    float s = 0.f;
#pragma unroll
    for (int i = 0; i < 6; i++) { v[i] = row[lane + 32*i]; s += v[i]; }
#pragma unroll
    for (int o = 16; o > 0; o >>= 1) s += __shfl_xor_sync(0xffffffffu, s, o);
    float mean = s * (1.0f / C);
    float s2 = 0.f;
#pragma unroll
    for (int i = 0; i < 6; i++) { float d = v[i] - mean; s2 += d * d; }
#pragma unroll
    for (int o = 16; o > 0; o >>= 1) s2 += __shfl_xor_sync(0xffffffffu, s2, o);
    float rstd = rsqrtf(s2 * (1.0f / C) + 1e-5f);
    bf16* orow = out + (size_t)token * C;
#pragma unroll
    for (int i = 0; i < 6; i++) {
        int cc = lane + 32*i;
        orow[cc] = __float2bfloat16((v[i] - mean) * rstd * g[cc] + b[cc]);
    }
}

// ---------------- bf16 tensor-core GEMM -------------------------------------
// OUT[M,N] = epi( A[M,K] @ W[K,N] + bias[N] )
// A: bf16 or fp32 (AIN_BF16), W/bias fp32, res fp32, OUT fp32 or bf16.
// BM=128, BN=96, BK=32, 256 threads = 8 warps 4(m)x2(n), warp tile 32x48.
// smem: uint2 element u = (pair k0, pair k0+8elems) so each fragment half is
// one LDS.64; xor-swizzled by row for conflict-freedom.

__device__ __forceinline__ void mma_bf16(float* d, const uint32_t* a,
                                         uint32_t b0, uint32_t b1) {
    asm volatile(
        "mma.sync.aligned.m16n8k16.row.col.f32.bf16.bf16.f32 "
        "{%0,%1,%2,%3},{%4,%5,%6,%7},{%8,%9},{%0,%1,%2,%3};"
        : "+f"(d[0]), "+f"(d[1]), "+f"(d[2]), "+f"(d[3])
        : "r"(a[0]), "r"(a[1]), "r"(a[2]), "r"(a[3]), "r"(b0), "r"(b1));
}

// store 16 staged floats (k-half h of a 32-k row) as 4 swizzled uint2
__device__ __forceinline__ void stage_f32(uint2* buf, int row, int h,
                                          const float* ar) {
#pragma unroll
    for (int j = 0; j < 4; j++) {
        uint2 u;
        u.x = bf2(ar[2*j],     ar[2*j + 1]);
        u.y = bf2(ar[2*j + 8], ar[2*j + 9]);
        buf[row * 8 + ((4*h + j) ^ (row & 7))] = u;
    }
}
__device__ __forceinline__ void stage_bf(uint2* buf, int row, int h,
                                         uint4 q0, uint4 q1) {
    uint32_t a0[4] = {q0.x, q0.y, q0.z, q0.w};
    uint32_t a1[4] = {q1.x, q1.y, q1.z, q1.w};
#pragma unroll
    for (int j = 0; j < 4; j++)
        buf[row * 8 + ((4*h + j) ^ (row & 7))] = make_uint2(a0[j], a1[j]);
}

template<int EPI, bool AIN_BF16, bool OUT_BF16>
__global__ void __launch_bounds__(256)
gemm_bf16(const void* __restrict__ Av, const float* __restrict__ W,
          const float* __restrict__ bias, const float* __restrict__ res,
          void* __restrict__ outv, int M, int N, int K) {
    __shared__ uint2 smu[2*1024 + 2*768];   // A0,A1 (128*8), B0,B1 (96*8)

    const int tid  = threadIdx.x;
    const int wid  = tid >> 5, lane = tid & 31;
    const int wm   = wid >> 1, wn = wid & 1;
    const int gid  = lane >> 2, tig = lane & 3;
    const int n0   = blockIdx.x * 96;
    const int m0   = blockIdx.y * 128;

    const int arow  = tid >> 1;
    const int ahalf = tid & 1;
    const int bn    = tid >> 1;
    const int bhalf = tid & 1;
    const bool bact = (tid < 192);

    const float* gAf = AIN_BF16 ? nullptr
        : (const float*)Av + (size_t)(m0 + arow) * K + ahalf * 16;
    const bf16*  gAb = AIN_BF16
        ? (const bf16*)Av + (size_t)(m0 + arow) * K + ahalf * 16 : nullptr;
    const float* gB  = W + n0 + bn;

    float acc[2][6][4];
#pragma unroll
    for (int mt = 0; mt < 2; mt++)
#pragma unroll
        for (int nt = 0; nt < 6; nt++)
#pragma unroll
            for (int r = 0; r < 4; r++) acc[mt][nt][r] = 0.f;

    float ar[16], br[16];
    uint4 q0, q1;
    const int nk = K / 32;

    // ---- prologue: stage tile 0 into buffer 0
    if (AIN_BF16) {
        q0 = ((const uint4*)gAb)[0];
        q1 = ((const uint4*)gAb)[1];
    } else {
#pragma unroll
        for (int q = 0; q < 4; q++)
            *(float4*)&ar[q*4] = *(const float4*)(gAf + q*4);
    }
    if (bact)
#pragma unroll
        for (int kk = 0; kk < 16; kk++)
            br[kk] = gB[(size_t)(bhalf*16 + kk) * N];

    if (AIN_BF16) stage_bf(smu, arow, ahalf, q0, q1);
    else          stage_f32(smu, arow, ahalf, ar);
    if (bact)     stage_f32(smu + 2048, bn, bhalf, br);
    __syncthreads();

    for (int kt = 0; kt < nk; kt++) {
        if (kt + 1 < nk) {
            if (AIN_BF16) {
                const uint4* p = (const uint4*)(gAb + (kt+1)*32);
                q0 = p[0]; q1 = p[1];
            } else {
                const float* pA = gAf + (kt+1)*32;
#pragma unroll
                for (int q = 0; q < 4; q++)
                    *(float4*)&ar[q*4] = *(const float4*)(pA + q*4);
            }
            if (bact) {
                const float* pB = gB + (size_t)(kt+1) * 32 * N;
#pragma unroll
                for (int kk = 0; kk < 16; kk++)
                    br[kk] = pB[(size_t)(bhalf*16 + kk) * N];
            }
        }

        const uint2* Ab = smu + (kt & 1) * 1024;
        const uint2* Bb = smu + 2048 + (kt & 1) * 768;
#pragma unroll
        for (int s = 0; s < 2; s++) {
            uint32_t af[2][4];
#pragma unroll
            for (int mt = 0; mt < 2; mt++) {
                int r0 = wm*32 + mt*16 + gid;
                uint2 va = Ab[r0*8       + ((4*s + tig) ^ (r0 & 7))];
                uint2 vb = Ab[(r0+8)*8   + ((4*s + tig) ^ (r0 & 7))];
                af[mt][0] = va.x; af[mt][1] = vb.x;
                af[mt][2] = va.y; af[mt][3] = vb.y;
            }
#pragma unroll
            for (int nt = 0; nt < 6; nt++) {
                int nn = wn*48 + nt*8 + gid;
                uint2 wv = Bb[nn*8 + ((4*s + tig) ^ (nn & 7))];
#pragma unroll
                for (int mt = 0; mt < 2; mt++)
                    mma_bf16(acc[mt][nt], af[mt], wv.x, wv.y);
            }
        }

        if (kt + 1 < nk) {
            uint2* Aw = smu + ((kt+1) & 1) * 1024;
            uint2* Bw = smu + 2048 + ((kt+1) & 1) * 768;
            __syncthreads();
            if (AIN_BF16) stage_bf(Aw, arow, ahalf, q0, q1);
            else          stage_f32(Aw, arow, ahalf, ar);
            if (bact)     stage_f32(Bw, bn, bhalf, br);
            __syncthreads();
        }
    }

    // ---- epilogue
#pragma unroll
    for (int nt = 0; nt < 6; nt++) {
        int cb = n0 + wn*48 + nt*8 + 2*tig;
        float b0 = bias[cb], b1 = bias[cb + 1];
#pragma unroll
        for (int mt = 0; mt < 2; mt++) {
            int r0 = m0 + wm*32 + mt*16 + gid;
#pragma unroll
            for (int hh = 0; hh < 2; hh++) {
                int r = r0 + hh*8;
                float v0 = acc[mt][nt][hh*2 + 0] + b0;
                float v1 = acc[mt][nt][hh*2 + 1] + b1;
                if (EPI == 1) { v0 = v0 * normcdff(v0); v1 = v1 * normcdff(v1); }
                if (EPI == 2) {
                    const float* rr = res + (size_t)r * N + cb;
                    v0 += rr[0]; v1 += rr[1];
                }
                if (OUT_BF16)
                    *(uint32_t*)((bf16*)outv + (size_t)r * N + cb) = bf2(v0, v1);
                else
                    *(float2*)((float*)outv + (size_t)r * N + cb) =
                        make_float2(v0, v1);
            }
        }
    }
}

// ---------------- fused window attention (bf16 I/O) -------------------------
__global__ void __launch_bounds__(384)
attn_kernel(const bf16* __restrict__ q, const bf16* __restrict__ kv,
            const float* __restrict__ table, bf16* __restrict__ aw) {
    __shared__ float ks[16*192];
    __shared__ float vs[16*192];
    __shared__ float tb[49*HEADS];

    int w  = blockIdx.x;
    int bb = w >> 10;
    int wi = w & 1023;
    int wy = wi >> 5, wx = wi & 31;
    size_t base = (size_t)bb * HW + (size_t)(wy*8) * IMW + wx*8;
    int tid = threadIdx.x;

    for (int e = tid; e < 49*HEADS; e += 384) tb[e] = table[e];

    // gather + permute kv -> k/v [16][192] (fp32 in smem)
    for (int e = tid; e < 64*48; e += 384) {
        int s  = e / 48, cc = e - s*48;
        int r  = s >> 3, c = s & 7;
        int p  = (r >> 1) * 4 + (c >> 1);
        int f  = (r & 1) * 96 + (c & 1) * 48 + cc;
        const bf16* src = kv + (base + (size_t)r * IMW + c) * (C/2);
        ks[p*192 + f] = __bfloat162float(src[cc]);
        vs[p*192 + f] = __bfloat162float(src[48 + cc]);
    }
    __syncthreads();

    int h  = tid / 64;
    int qt = tid & 63;
    int r  = qt >> 3, c = qt & 7;
    int ph = r >> 1, pw = c >> 1;

    size_t tok = base + (size_t)r * IMW + c;
    const uint4* q4 = (const uint4*)(q + tok * C + h*HD);
    float qr[HD];
#pragma unroll
    for (int i = 0; i < 4; i++) {
        uint4 t = q4[i];
        uint32_t u[4] = {t.x, t.y, t.z, t.w};
#pragma unroll
        for (int j = 0; j < 4; j++) {
            float2 f2 = __bfloat1622float2(*(bf162*)&u[j]);
            qr[i*8 + 2*j]     = f2.x * SCALE_Q;
            qr[i*8 + 2*j + 1] = f2.y * SCALE_Q;
        }
    }

    float s[16], m = -1e30f;
#pragma unroll
    for (int kt = 0; kt < 16; kt++) {
        int kh = kt >> 2, kw = kt & 3;
        float acc = tb[((ph - kh + 3) * 7 + (pw - kw + 3)) * HEADS + h];
        const float* kr = &ks[kt*192 + h*HD];
#pragma unroll
        for (int d = 0; d < HD; d++) acc += qr[d] * kr[d];
        s[kt] = acc;
        m = fmaxf(m, acc);
    }
    float sum = 0.f;
#pragma unroll
    for (int kt = 0; kt < 16; kt++) { s[kt] = __expf(s[kt] - m); sum += s[kt]; }
    float inv = 1.0f / sum;

    float ov[HD];
#pragma unroll
    for (int d = 0; d < HD; d++) {
        float o = 0.f;
#pragma unroll
        for (int kt = 0; kt < 16; kt++) o += s[kt] * vs[kt*192 + h*HD + d];
        ov[d] = o * inv;
    }
    // direct bf16 writeback: 64B contiguous per thread
    uint4* ow = (uint4*)(aw + tok * C + h*HD);
#pragma unroll
    for (int i = 0; i < 4; i++) {
        uint4 t;
        t.x = bf2(ov[i*8+0], ov[i*8+1]);
        t.y = bf2(ov[i*8+2], ov[i*8+3]);
        t.z = bf2(ov[i*8+4], ov[i*8+5]);
        t.w = bf2(ov[i*8+6], ov[i*8+7]);
        ow[i] = t;
    }
}

// ---------------- depthwise 5x5 conv + gelu + add (bf16 I/O) ----------------
// h2 = h1 + gelu(dwconv5x5(h1) + dwb); residual taken from the smem tile.
__global__ void __launch_bounds__(256)
dwconv_kernel(const bf16* __restrict__ h1, const float* __restrict__ dwk,
              const float* __restrict__ dwb, bf16* __restrict__ out) {
    constexpr int TS = 16, CCH = 32, TT = TS + 4;
    extern __shared__ float smem[];
    float* tile = smem;                 // [20][20][32] fp32
    float* wk   = tile + TT*TT*CCH;     // [32][25]
    float* bk   = wk + CCH*25;          // [32]

    int bz = blockIdx.z;
    int bb = bz / (HIDDEN / CCH);
    int c0 = (bz % (HIDDEN / CCH)) * CCH;
    int x0 = blockIdx.x * TS, y0 = blockIdx.y * TS;
    int tid = threadIdx.x;

    for (int e = tid; e < CCH*25; e += 256) {
        int cc = e / 25, t = e - cc*25;
        wk[cc*25 + t] = dwk[(c0 + cc) * 25 + t];
    }
    if (tid < CCH) bk[tid] = dwb[c0 + tid];

    // load 20x20 x 32ch halo tile from bf16, zero outside
    for (int e = tid; e < TT*TT*(CCH/8); e += 256) {
        int pos = e / (CCH/8);
        int qv  = e - pos*(CCH/8);          // which 8-ch chunk
        int py = pos / TT, px = pos - py*TT;
        int gy = y0 + py - 2, gx = x0 + px - 2;
        float f[8] = {0,0,0,0,0,0,0,0};
        if (gy >= 0 && gy < IMH && gx >= 0 && gx < IMW) {
            uint4 t = *(const uint4*)(h1 +
                ((size_t)bb*HW + (size_t)gy*IMW + gx)*HIDDEN + c0 + qv*8);
            uint32_t u[4] = {t.x, t.y, t.z, t.w};
#pragma unroll
            for (int j = 0; j < 4; j++) {
                float2 f2 = __bfloat1622float2(*(bf162*)&u[j]);
                f[2*j] = f2.x; f[2*j+1] = f2.y;
            }
        }
        float* dst = &tile[(py*TT + px)*CCH + qv*8];
#pragma unroll
        for (int j = 0; j < 8; j++) dst[j] = f[j];
    }
    __syncthreads();

    int cc = tid & (CCH-1);
    int st = tid >> 5;                  // 0..7
    const float* wr = &wk[cc*25];
    float bia = bk[cc];

    for (int it = 0; it < 8; it++) {
        int task = it*8 + st;           // 64 tasks: x(16) * ystrip(4)
        int x  = task & 15;
        int ys = task >> 4;
        float acc[4] = {0.f, 0.f, 0.f, 0.f};
#pragma unroll
        for (int rr = 0; rr < 8; rr++) {
            int py = ys*4 + rr;
            float v[5];
#pragma unroll
            for (int dx = 0; dx < 5; dx++)
                v[dx] = tile[(py*TT + x + dx)*CCH + cc];
#pragma unroll
            for (int j = 0; j < 4; j++) {
                int ky = rr - j;
                if (ky >= 0 && ky < 5) {
#pragma unroll
                    for (int dx = 0; dx < 5; dx++)
                        acc[j] += v[dx] * wr[ky*5 + dx];
                }
            }
        }
#pragma unroll
        for (int j = 0; j < 4; j++) {
            int y = ys*4 + j;
            float rj = tile[((y+2)*TT + (x+2))*CCH + cc];
            float gv = acc[j] + bia;
            gv = gv * normcdff(gv);
            size_t o = ((size_t)bb*HW + (size_t)(y0+y)*IMW + (x0+x))*HIDDEN
                     + c0 + cc;
            out[o] = __float2bfloat16(rj + gv);
        }
    }
}

// ---------------- launch ----------------------------------------------------
extern "C" void kernel_launch(void* const* d_in, const int* in_sizes, int n_in,
                              void* d_out, int out_size) {
    const float* x     = (const float*)d_in[0];
    const float* g1    = (const float*)d_in[1];
    const float* be1   = (const float*)d_in[2];
    const float* wq    = (const float*)d_in[3];
    const float* bq    = (const float*)d_in[4];
    const float* wkv   = (const float*)d_in[5];
    const float* bkv   = (const float*)d_in[6];
    const float* table = (const float*)d_in[7];
    const float* wproj = (const float*)d_in[8];
    const float* bproj = (const float*)d_in[9];
    const float* g2    = (const float*)d_in[10];
    const float* be2   = (const float*)d_in[11];
    const float* w1f   = (const float*)d_in[12];
    const float* b1f   = (const float*)d_in[13];
    const float* dwk   = (const float*)d_in[14];
    const float* dwb   = (const float*)d_in[15];
    const float* w2f   = (const float*)d_in[16];
    const float* b2f   = (const float*)d_in[17];
    float* out = (float*)d_out;

    void *pxn, *pq, *pkv, *paw, *pxmid, *ph1, *ph2;
    cudaGetSymbolAddress(&pxn,   g_xn);
    cudaGetSymbolAddress(&pq,    g_q);
    cudaGetSymbolAddress(&pkv,   g_kv);
    cudaGetSymbolAddress(&paw,   g_aw);
    cudaGetSymbolAddress(&pxmid, g_xmid);
    cudaGetSymbolAddress(&ph1,   g_h1);
    cudaGetSymbolAddress(&ph2,   g_h2);
    bf16*  xn   = (bf16*)pxn;
    bf16*  qb   = (bf16*)pq;
    bf16*  kvb  = (bf16*)pkv;
    bf16*  awb  = (bf16*)paw;
    float* xmid = (float*)pxmid;
    bf16*  h1   = (bf16*)ph1;
    bf16*  h2   = (bf16*)ph2;

    const int CSMEM = (20*20*32 + 32*25 + 32) * 4;
    cudaFuncSetAttribute(dwconv_kernel, cudaFuncAttributeMaxDynamicSharedMemorySize, CSMEM);

    dim3 lnb(32, 8);
    const int MB = M_TOK / 128;   // 1024 m-blocks

    // 1) LN1 -> xn (bf16)
    ln_kernel<<<M_TOK/8, lnb>>>(x, g1, be1, xn);
    // 2) q = xn @ wq + bq                 (bf16 in, bf16 out)
    gemm_bf16<0, true, true><<<dim3(2, MB), 256>>>(xn, wq, bq, nullptr, qb, M_TOK, 192, 192);
    // 3) kv = xn @ wkv + bkv
    gemm_bf16<0, true, true><<<dim3(1, MB), 256>>>(xn, wkv, bkv, nullptr, kvb, M_TOK, 96, 192);
    // 4) window attention -> aw (bf16)
    attn_kernel<<<2048, 384>>>(qb, kvb, table, awb);
    // 5) xmid = x + aw @ wproj + bproj    (fp32 out)
    gemm_bf16<2, true, false><<<dim3(2, MB), 256>>>(awb, wproj, bproj, x, xmid, M_TOK, 192, 192);
    // 6) LN2 -> xn (bf16)
    ln_kernel<<<M_TOK/8, lnb>>>(xmid, g2, be2, xn);
    // 7) h1 = gelu(xn @ w1f + b1f)        (bf16 out)
    gemm_bf16<1, true, true><<<dim3(8, MB), 256>>>(xn, w1f, b1f, nullptr, h1, M_TOK, 768, 192);
    // 8) h2 = h1 + gelu(dwconv(h1) + dwb) (bf16)
    dwconv_kernel<<<dim3(IMW/16, IMH/16, BATCH*(HIDDEN/32)), 256, CSMEM>>>(h1, dwk, dwb, h2);
    // 9) out = xmid + h2 @ w2f + b2f      (fp32 out, K=768)
    gemm_bf16<2, true, false><<<dim3(2, MB), 256>>>(h2, w2f, b2f, xmid, out, M_TOK, 192, 768);
}

// round 7
// speedup vs baseline: 2.7384x; 1.0181x over previous
#include <cuda_runtime.h>
#include <cuda_bf16.h>
#include <math.h>
#include <stdint.h>

#define BATCH   2
#define IMH     256
#define IMW     256
#define C       192
#define HEADS   6
#define HD      32
#define HIDDEN  768
#define HW      (IMH*IMW)
#define M_TOK   (BATCH*HW)          // 131072
#define SCALE_Q 0.17677669529663687f

typedef __nv_bfloat16  bf16;
typedef __nv_bfloat162 bf162;

// ---------------- scratch buffers (device globals; no allocation) -----------
__device__ bf16  g_xn  [M_TOK * C];
__device__ bf16  g_q   [M_TOK * C];
__device__ bf16  g_kv  [M_TOK * (C/2)];
__device__ bf16  g_aw  [M_TOK * C];
__device__ float g_xmid[M_TOK * C];
__device__ bf16  g_h1  [(size_t)M_TOK * HIDDEN];
__device__ bf16  g_h2  [(size_t)M_TOK * HIDDEN];
// packed bf16 weights, [N][K] row-major (B operand, K-contiguous)
__device__ bf16  g_wp  [387072];
#define WP_Q    0
#define WP_KV   36864
#define WP_PROJ 55296
#define WP_F1   92160
#define WP_F2   239616

__device__ __forceinline__ uint32_t bf2(float lo, float hi) {
    bf162 h = __floats2bfloat162_rn(lo, hi);
    return *(uint32_t*)&h;
}

// ---------------- weight pre-pack (all 5 matrices, one launch) --------------
// out[n*K+k] = bf16(W[k*N+n]) per segment.
__global__ void pack_all(const float* __restrict__ wq,
                         const float* __restrict__ wkv,
                         const float* __restrict__ wproj,
                         const float* __restrict__ w1f,
                         const float* __restrict__ w2f,
                         bf16* __restrict__ out) {
    int idx = blockIdx.x * 256 + threadIdx.x;
    if (idx >= 387072) return;
    const float* W; int K, N, off;
    if      (idx < WP_KV)   { W = wq;    K = 192; N = 192; off = WP_Q;    }
    else if (idx < WP_PROJ) { W = wkv;   K = 192; N = 96;  off = WP_KV;   }
    else if (idx < WP_F1)   { W = wproj; K = 192; N = 192; off = WP_PROJ; }
    else if (idx < WP_F2)   { W = w1f;   K = 192; N = 768; off = WP_F1;   }
    else                    { W = w2f;   K = 768; N = 192; off = WP_F2;   }
    int li = idx - off;
    int n = li / K, k = li - n * K;
    out[idx] = __float2bfloat16(W[(size_t)k * N + n]);
}

// ---------------- LayerNorm: one warp per token, contiguous 6/thread --------
__global__ void ln_kernel(const float* __restrict__ x,
                          const float* __restrict__ g,
                          const float* __restrict__ b,
                          bf16* __restrict__ out) {
    int token = blockIdx.x * blockDim.y + threadIdx.y;
    int lane  = threadIdx.x;
    const float* row = x + (size_t)token * C + lane * 6;
    float v[6];
#pragma unroll
    for (int i = 0; i < 3; i++)
        *(float2*)&v[2*i] = *(const float2*)(row + 2*i);
    float s = 0.f;
#pragma unroll
    for (int i = 0; i < 6; i++) s += v[i];
#pragma unroll
    for (int o = 16; o > 0; o >>= 1) s += __shfl_xor_sync(0xffffffffu, s, o);
    float mean = s * (1.0f / C);
    float s2 = 0.f;
#pragma unroll
    for (int i = 0; i < 6; i++) { float d = v[i] - mean; s2 += d * d; }
#pragma unroll
    for (int o = 16; o > 0; o >>= 1) s2 += __shfl_xor_sync(0xffffffffu, s2, o);
    float rstd = rsqrtf(s2 * (1.0f / C) + 1e-5f);
    float gv[6], bv[6];
#pragma unroll
    for (int i = 0; i < 3; i++) {
        *(float2*)&gv[2*i] = *(const float2*)(g + lane*6 + 2*i);
        *(float2*)&bv[2*i] = *(const float2*)(b + lane*6 + 2*i);
    }
    uint32_t* orow = (uint32_t*)(out + (size_t)token * C + lane * 6);
#pragma unroll
    for (int i = 0; i < 3; i++) {
        float a0 = (v[2*i]   - mean) * rstd * gv[2*i]   + bv[2*i];
        float a1 = (v[2*i+1] - mean) * rstd * gv[2*i+1] + bv[2*i+1];
        orow[i] = bf2(a0, a1);
    }
}

// ---------------- bf16 tensor-core GEMM -------------------------------------
// OUT[M,N] = epi( A[M,K] @ Wp^T + bias )  with Wp packed [N][K] bf16.
// BM=128, BN=96, BK=32, 256 threads = 8 warps 4(m)x2(n), warp tile 32x48.
// smem uint2 = (bf16-pair k, pair k+8 elems); xor-swizzled per row; each
// fragment half is one LDS.64. Single __syncthreads per k-tile.

__device__ __forceinline__ void mma_bf16(float* d, const uint32_t* a,
                                         uint32_t b0, uint32_t b1) {
    asm volatile(
        "mma.sync.aligned.m16n8k16.row.col.f32.bf16.bf16.f32 "
        "{%0,%1,%2,%3},{%4,%5,%6,%7},{%8,%9},{%0,%1,%2,%3};"
        : "+f"(d[0]), "+f"(d[1]), "+f"(d[2]), "+f"(d[3])
        : "r"(a[0]), "r"(a[1]), "r"(a[2]), "r"(a[3]), "r"(b0), "r"(b1));
}

__device__ __forceinline__ void stage_bf(uint2* buf, int row, int h,
                                         uint4 q0, uint4 q1) {
    uint32_t a0[4] = {q0.x, q0.y, q0.z, q0.w};
    uint32_t a1[4] = {q1.x, q1.y, q1.z, q1.w};
#pragma unroll
    for (int j = 0; j < 4; j++)
        buf[row * 8 + ((4*h + j) ^ (row & 7))] = make_uint2(a0[j], a1[j]);
}

#define GEMM_SMEM (2*1024 + 2*768)   // uint2 elems = 28672 bytes

template<int EPI, bool OUT_BF16>
__device__ __forceinline__ void
gemm_body(uint2* smu, const bf16* __restrict__ A, const bf16* __restrict__ Wp,
          const float* __restrict__ bias, const float* __restrict__ res,
          void* __restrict__ outv, int N, int K, int n0, int m0) {
    const int tid  = threadIdx.x;
    const int wid  = tid >> 5, lane = tid & 31;
    const int wm   = wid >> 1, wn = wid & 1;
    const int gid  = lane >> 2, tig = lane & 3;

    const int arow  = tid >> 1;
    const int ahalf = tid & 1;
    const int bn    = tid >> 1;
    const int bhalf = tid & 1;
    const bool bact = (tid < 192);

    const bf16* gA = A  + (size_t)(m0 + arow) * K + ahalf * 16;
    const bf16* gB = Wp + (size_t)(n0 + bn)   * K + bhalf * 16;

    float acc[2][6][4];
#pragma unroll
    for (int mt = 0; mt < 2; mt++)
#pragma unroll
        for (int nt = 0; nt < 6; nt++)
#pragma unroll
            for (int r = 0; r < 4; r++) acc[mt][nt][r] = 0.f;

    uint4 qa0, qa1, qb0, qb1;
    const int nk = K / 32;

    // prologue: stage tile 0 -> buf 0
    qa0 = ((const uint4*)gA)[0]; qa1 = ((const uint4*)gA)[1];
    if (bact) { qb0 = ((const uint4*)gB)[0]; qb1 = ((const uint4*)gB)[1]; }
    stage_bf(smu, arow, ahalf, qa0, qa1);
    if (bact) stage_bf(smu + 2048, bn, bhalf, qb0, qb1);
    __syncthreads();

    for (int kt = 0; kt < nk; kt++) {
        if (kt + 1 < nk) {
            const uint4* pA = (const uint4*)(gA + (kt+1)*32);
            qa0 = pA[0]; qa1 = pA[1];
            if (bact) {
                const uint4* pB = (const uint4*)(gB + (kt+1)*32);
                qb0 = pB[0]; qb1 = pB[1];
            }
        }
        const uint2* Ab = smu + (kt & 1) * 1024;
        const uint2* Bb = smu + 2048 + (kt & 1) * 768;
#pragma unroll
        for (int s = 0; s < 2; s++) {
            uint32_t af[2][4];
#pragma unroll
            for (int mt = 0; mt < 2; mt++) {
                int r0 = wm*32 + mt*16 + gid;
                uint2 va = Ab[r0*8     + ((4*s + tig) ^ (r0 & 7))];
                uint2 vb = Ab[(r0+8)*8 + ((4*s + tig) ^ (r0 & 7))];
                af[mt][0] = va.x; af[mt][1] = vb.x;
                af[mt][2] = va.y; af[mt][3] = vb.y;
            }
#pragma unroll
            for (int nt = 0; nt < 6; nt++) {
                int nn = wn*48 + nt*8 + gid;
                uint2 wv = Bb[nn*8 + ((4*s + tig) ^ (nn & 7))];
#pragma unroll
                for (int mt = 0; mt < 2; mt++)
                    mma_bf16(acc[mt][nt], af[mt], wv.x, wv.y);
            }
        }
        if (kt + 1 < nk) {
            uint2* Aw = smu + ((kt+1) & 1) * 1024;
            uint2* Bw = smu + 2048 + ((kt+1) & 1) * 768;
            stage_bf(Aw, arow, ahalf, qa0, qa1);
            if (bact) stage_bf(Bw, bn, bhalf, qb0, qb1);
            __syncthreads();
        }
    }

    // epilogue
#pragma unroll
    for (int nt = 0; nt < 6; nt++) {
        int cb = n0 + wn*48 + nt*8 + 2*tig;
        float b0 = bias[cb], b1 = bias[cb + 1];
#pragma unroll
        for (int mt = 0; mt < 2; mt++) {
            int r0 = m0 + wm*32 + mt*16 + gid;
#pragma unroll
            for (int hh = 0; hh < 2; hh++) {
                int r = r0 + hh*8;
                float v0 = acc[mt][nt][hh*2 + 0] + b0;
                float v1 = acc[mt][nt][hh*2 + 1] + b1;
                if (EPI == 1) { v0 = v0 * normcdff(v0); v1 = v1 * normcdff(v1); }
                if (EPI == 2) {
                    const float* rr = res + (size_t)r * N + cb;
                    v0 += rr[0]; v1 += rr[1];
                }
                if (OUT_BF16)
                    *(uint32_t*)((bf16*)outv + (size_t)r * N + cb) = bf2(v0, v1);
                else
                    *(float2*)((float*)outv + (size_t)r * N + cb) =
                        make_float2(v0, v1);
            }
        }
    }
}

template<int EPI, bool OUT_BF16>
__global__ void __launch_bounds__(256)
gemm_k(const bf16* __restrict__ A, const bf16* __restrict__ Wp,
       const float* __restrict__ bias, const float* __restrict__ res,
       void* __restrict__ out, int N, int K) {
    __shared__ uint2 smu[GEMM_SMEM];
    gemm_body<EPI, OUT_BF16>(smu, A, Wp, bias, res, out, N, K,
                             blockIdx.x * 96, blockIdx.y * 128);
}

// fused q + kv projection (shares the A read of xn)
__global__ void __launch_bounds__(256)
gemm_qkv(const bf16* __restrict__ A,
         const bf16* __restrict__ Wq,  const float* __restrict__ bq,
         bf16* __restrict__ qout,
         const bf16* __restrict__ Wkv, const float* __restrict__ bkv,
         bf16* __restrict__ kvout) {
    __shared__ uint2 smu[GEMM_SMEM];
    if (blockIdx.x < 2)
        gemm_body<0, true>(smu, A, Wq, bq, nullptr, qout, 192, 192,
                           blockIdx.x * 96, blockIdx.y * 128);
    else
        gemm_body<0, true>(smu, A, Wkv, bkv, nullptr, kvout, 96, 192,
                           0, blockIdx.y * 128);
}

// ---------------- fused window attention (bf16 I/O) -------------------------
__global__ void __launch_bounds__(384)
attn_kernel(const bf16* __restrict__ q, const bf16* __restrict__ kv,
            const float* __restrict__ table, bf16* __restrict__ aw) {
    __shared__ float ks[16*192];
    __shared__ float vs[16*192];
    __shared__ float tb[49*HEADS];

    int w  = blockIdx.x;
    int bb = w >> 10;
    int wi = w & 1023;
    int wy = wi >> 5, wx = wi & 31;
    size_t base = (size_t)bb * HW + (size_t)(wy*8) * IMW + wx*8;
    int tid = threadIdx.x;

    for (int e = tid; e < 49*HEADS; e += 384) tb[e] = table[e];

    for (int e = tid; e < 64*48; e += 384) {
        int s  = e / 48, cc = e - s*48;
        int r  = s >> 3, c = s & 7;
        int p  = (r >> 1) * 4 + (c >> 1);
        int f  = (r & 1) * 96 + (c & 1) * 48 + cc;
        const bf16* src = kv + (base + (size_t)r * IMW + c) * (C/2);
        ks[p*192 + f] = __bfloat162float(src[cc]);
        vs[p*192 + f] = __bfloat162float(src[48 + cc]);
    }
    __syncthreads();

    int h  = tid / 64;
    int qt = tid & 63;
    int r  = qt >> 3, c = qt & 7;
    int ph = r >> 1, pw = c >> 1;

    size_t tok = base + (size_t)r * IMW + c;
    const uint4* q4 = (const uint4*)(q + tok * C + h*HD);
    float qr[HD];
#pragma unroll
    for (int i = 0; i < 4; i++) {
        uint4 t = q4[i];
        uint32_t u[4] = {t.x, t.y, t.z, t.w};
#pragma unroll
        for (int j = 0; j < 4; j++) {
            float2 f2 = __bfloat1622float2(*(bf162*)&u[j]);
            qr[i*8 + 2*j]     = f2.x * SCALE_Q;
            qr[i*8 + 2*j + 1] = f2.y * SCALE_Q;
        }
    }

    float s[16], m = -1e30f;
#pragma unroll
    for (int kt = 0; kt < 16; kt++) {
        int kh = kt >> 2, kw = kt & 3;
        float acc = tb[((ph - kh + 3) * 7 + (pw - kw + 3)) * HEADS + h];
        const float* kr = &ks[kt*192 + h*HD];
#pragma unroll
        for (int d = 0; d < HD; d++) acc += qr[d] * kr[d];
        s[kt] = acc;
        m = fmaxf(m, acc);
    }
    float sum = 0.f;
#pragma unroll
    for (int kt = 0; kt < 16; kt++) { s[kt] = __expf(s[kt] - m); sum += s[kt]; }
    float inv = 1.0f / sum;

    float ov[HD];
#pragma unroll
    for (int d = 0; d < HD; d++) {
        float o = 0.f;
#pragma unroll
        for (int kt = 0; kt < 16; kt++) o += s[kt] * vs[kt*192 + h*HD + d];
        ov[d] = o * inv;
    }
    uint4* ow = (uint4*)(aw + tok * C + h*HD);
#pragma unroll
    for (int i = 0; i < 4; i++) {
        uint4 t;
        t.x = bf2(ov[i*8+0], ov[i*8+1]);
        t.y = bf2(ov[i*8+2], ov[i*8+3]);
        t.z = bf2(ov[i*8+4], ov[i*8+5]);
        t.w = bf2(ov[i*8+6], ov[i*8+7]);
        ow[i] = t;
    }
}

// ---------------- depthwise 5x5 conv + gelu + add (bf16 I/O) ----------------
__global__ void __launch_bounds__(256)
dwconv_kernel(const bf16* __restrict__ h1, const float* __restrict__ dwk,
              const float* __restrict__ dwb, bf16* __restrict__ out) {
    constexpr int TS = 16, CCH = 32, TT = TS + 4;
    extern __shared__ float smem[];
    float* tile = smem;                 // [20][20][32] fp32
    float* wk   = tile + TT*TT*CCH;     // [32][25]
    float* bk   = wk + CCH*25;          // [32]

    int bz = blockIdx.z;
    int bb = bz / (HIDDEN / CCH);
    int c0 = (bz % (HIDDEN / CCH)) * CCH;
    int x0 = blockIdx.x * TS, y0 = blockIdx.y * TS;
    int tid = threadIdx.x;

    for (int e = tid; e < CCH*25; e += 256) {
        int cc = e / 25, t = e - cc*25;
        wk[cc*25 + t] = dwk[(c0 + cc) * 25 + t];
    }
    if (tid < CCH) bk[tid] = dwb[c0 + tid];

    for (int e = tid; e < TT*TT*(CCH/8); e += 256) {
        int pos = e / (CCH/8);
        int qv  = e - pos*(CCH/8);
        int py = pos / TT, px = pos - py*TT;
        int gy = y0 + py - 2, gx = x0 + px - 2;
        float f[8] = {0,0,0,0,0,0,0,0};
        if (gy >= 0 && gy < IMH && gx >= 0 && gx < IMW) {
            uint4 t = *(const uint4*)(h1 +
                ((size_t)bb*HW + (size_t)gy*IMW + gx)*HIDDEN + c0 + qv*8);
            uint32_t u[4] = {t.x, t.y, t.z, t.w};
#pragma unroll
            for (int j = 0; j < 4; j++) {
                float2 f2 = __bfloat1622float2(*(bf162*)&u[j]);
                f[2*j] = f2.x; f[2*j+1] = f2.y;
            }
        }
        float* dst = &tile[(py*TT + px)*CCH + qv*8];
#pragma unroll
        for (int j = 0; j < 8; j++) dst[j] = f[j];
    }
    __syncthreads();

    int cc = tid & (CCH-1);
    int st = tid >> 5;
    const float* wr = &wk[cc*25];
    float bia = bk[cc];

    for (int it = 0; it < 8; it++) {
        int task = it*8 + st;
        int x  = task & 15;
        int ys = task >> 4;
        float acc[4] = {0.f, 0.f, 0.f, 0.f};
#pragma unroll
        for (int rr = 0; rr < 8; rr++) {
            int py = ys*4 + rr;
            float v[5];
#pragma unroll
            for (int dx = 0; dx < 5; dx++)
                v[dx] = tile[(py*TT + x + dx)*CCH + cc];
#pragma unroll
            for (int j = 0; j < 4; j++) {
                int ky = rr - j;
                if (ky >= 0 && ky < 5) {
#pragma unroll
                    for (int dx = 0; dx < 5; dx++)
                        acc[j] += v[dx] * wr[ky*5 + dx];
                }
            }
        }
#pragma unroll
        for (int j = 0; j < 4; j++) {
            int y = ys*4 + j;
            float rj = tile[((y+2)*TT + (x+2))*CCH + cc];
            float gv = acc[j] + bia;
            gv = gv * normcdff(gv);
            size_t o = ((size_t)bb*HW + (size_t)(y0+y)*IMW + (x0+x))*HIDDEN
                     + c0 + cc;
            out[o] = __float2bfloat16(rj + gv);
        }
    }
}

// ---------------- launch ----------------------------------------------------
extern "C" void kernel_launch(void* const* d_in, const int* in_sizes, int n_in,
                              void* d_out, int out_size) {
    const float* x     = (const float*)d_in[0];
    const float* g1    = (const float*)d_in[1];
    const float* be1   = (const float*)d_in[2];
    const float* wq    = (const float*)d_in[3];
    const float* bq    = (const float*)d_in[4];
    const float* wkv   = (const float*)d_in[5];
    const float* bkv   = (const float*)d_in[6];
    const float* table = (const float*)d_in[7];
    const float* wproj = (const float*)d_in[8];
    const float* bproj = (const float*)d_in[9];
    const float* g2    = (const float*)d_in[10];
    const float* be2   = (const float*)d_in[11];
    const float* w1f   = (const float*)d_in[12];
    const float* b1f   = (const float*)d_in[13];
    const float* dwk   = (const float*)d_in[14];
    const float* dwb   = (const float*)d_in[15];
    const float* w2f   = (const float*)d_in[16];
    const float* b2f   = (const float*)d_in[17];
    float* out = (float*)d_out;

    void *pxn, *pq, *pkv, *paw, *pxmid, *ph1, *ph2, *pwp;
    cudaGetSymbolAddress(&pxn,   g_xn);
    cudaGetSymbolAddress(&pq,    g_q);
    cudaGetSymbolAddress(&pkv,   g_kv);
    cudaGetSymbolAddress(&paw,   g_aw);
    cudaGetSymbolAddress(&pxmid, g_xmid);
    cudaGetSymbolAddress(&ph1,   g_h1);
    cudaGetSymbolAddress(&ph2,   g_h2);
    cudaGetSymbolAddress(&pwp,   g_wp);
    bf16*  xn   = (bf16*)pxn;
    bf16*  qb   = (bf16*)pq;
    bf16*  kvb  = (bf16*)pkv;
    bf16*  awb  = (bf16*)paw;
    float* xmid = (float*)pxmid;
    bf16*  h1   = (bf16*)ph1;
    bf16*  h2   = (bf16*)ph2;
    bf16*  wp   = (bf16*)pwp;

    const int CSMEM = (20*20*32 + 32*25 + 32) * 4;
    cudaFuncSetAttribute(dwconv_kernel, cudaFuncAttributeMaxDynamicSharedMemorySize, CSMEM);

    dim3 lnb(32, 8);
    const int MB = M_TOK / 128;   // 1024 m-blocks

    // 0) pack all weights to bf16 [N][K] (one launch)
    pack_all<<<(387072 + 255)/256, 256>>>(wq, wkv, wproj, w1f, w2f, wp);

    // 1) LN1 -> xn (bf16)
    ln_kernel<<<M_TOK/8, lnb>>>(x, g1, be1, xn);
    // 2+3) fused q & kv projections
    gemm_qkv<<<dim3(3, MB), 256>>>(xn, wp + WP_Q, bq, qb,
                                   wp + WP_KV, bkv, kvb);
    // 4) window attention -> aw (bf16)
    attn_kernel<<<2048, 384>>>(qb, kvb, table, awb);
    // 5) xmid = x + aw @ wproj + bproj (fp32 out)
    gemm_k<2, false><<<dim3(2, MB), 256>>>(awb, wp + WP_PROJ, bproj, x, xmid, 192, 192);
    // 6) LN2 -> xn
    ln_kernel<<<M_TOK/8, lnb>>>(xmid, g2, be2, xn);
    // 7) h1 = gelu(xn @ w1f + b1f)
    gemm_k<1, true><<<dim3(8, MB), 256>>>(xn, wp + WP_F1, b1f, nullptr, h1, 768, 192);
    // 8) h2 = h1 + gelu(dwconv(h1) + dwb)
    dwconv_kernel<<<dim3(IMW/16, IMH/16, BATCH*(HIDDEN/32)), 256, CSMEM>>>(h1, dwk, dwb, h2);
    // 9) out = xmid + h2 @ w2f + b2f (fp32 out, K=768)
    gemm_k<2, false><<<dim3(2, MB), 256>>>(h2, wp + WP_F2, b2f, xmid, out, 192, 768);
}

// round 8
// speedup vs baseline: 3.5096x; 1.2816x over previous
#include <cuda_runtime.h>
#include <cuda_bf16.h>
#include <math.h>
#include <stdint.h>

#define BATCH   2
#define IMH     256
#define IMW     256
#define C       192
#define HEADS   6
#define HD      32
#define HIDDEN  768
#define HW      (IMH*IMW)
#define M_TOK   (BATCH*HW)          // 131072
#define SCALE_Q 0.17677669529663687f

typedef __nv_bfloat16  bf16;
typedef __nv_bfloat162 bf162;

// ---------------- scratch buffers (device globals; no allocation) -----------
__device__ bf16  g_xn  [M_TOK * C];
__device__ bf16  g_q   [M_TOK * C];
__device__ bf16  g_kv  [M_TOK * (C/2)];
__device__ bf16  g_aw  [M_TOK * C];
__device__ float g_xmid[M_TOK * C];
__device__ bf16  g_h1  [(size_t)M_TOK * HIDDEN];
__device__ bf16  g_h2  [(size_t)M_TOK * HIDDEN];
// packed bf16 weights, [N][K] row-major (B operand, K-contiguous)
__device__ bf16  g_wp  [387072];
#define WP_Q    0
#define WP_KV   36864
#define WP_PROJ 55296
#define WP_F1   92160
#define WP_F2   239616

__device__ __forceinline__ uint32_t bf2(float lo, float hi) {
    bf162 h = __floats2bfloat162_rn(lo, hi);
    return *(uint32_t*)&h;
}

// ---------------- weight pre-pack (all 5 matrices, one launch) --------------
__global__ void pack_all(const float* __restrict__ wq,
                         const float* __restrict__ wkv,
                         const float* __restrict__ wproj,
                         const float* __restrict__ w1f,
                         const float* __restrict__ w2f,
                         bf16* __restrict__ out) {
    int idx = blockIdx.x * 256 + threadIdx.x;
    if (idx >= 387072) return;
    const float* W; int K, N, off;
    if      (idx < WP_KV)   { W = wq;    K = 192; N = 192; off = WP_Q;    }
    else if (idx < WP_PROJ) { W = wkv;   K = 192; N = 96;  off = WP_KV;   }
    else if (idx < WP_F1)   { W = wproj; K = 192; N = 192; off = WP_PROJ; }
    else if (idx < WP_F2)   { W = w1f;   K = 192; N = 768; off = WP_F1;   }
    else                    { W = w2f;   K = 768; N = 192; off = WP_F2;   }
    int li = idx - off;
    int n = li / K, k = li - n * K;
    out[idx] = __float2bfloat16(W[(size_t)k * N + n]);
}

// ---------------- LayerNorm: one warp per token, contiguous 6/thread --------
__global__ void ln_kernel(const float* __restrict__ x,
                          const float* __restrict__ g,
                          const float* __restrict__ b,
                          bf16* __restrict__ out) {
    int token = blockIdx.x * blockDim.y + threadIdx.y;
    int lane  = threadIdx.x;
    const float* row = x + (size_t)token * C + lane * 6;
    float v[6];
#pragma unroll
    for (int i = 0; i < 3; i++)
        *(float2*)&v[2*i] = *(const float2*)(row + 2*i);
    float s = 0.f;
#pragma unroll
    for (int i = 0; i < 6; i++) s += v[i];
#pragma unroll
    for (int o = 16; o > 0; o >>= 1) s += __shfl_xor_sync(0xffffffffu, s, o);
    float mean = s * (1.0f / C);
    float s2 = 0.f;
#pragma unroll
    for (int i = 0; i < 6; i++) { float d = v[i] - mean; s2 += d * d; }
#pragma unroll
    for (int o = 16; o > 0; o >>= 1) s2 += __shfl_xor_sync(0xffffffffu, s2, o);
    float rstd = rsqrtf(s2 * (1.0f / C) + 1e-5f);
    float gv[6], bv[6];
#pragma unroll
    for (int i = 0; i < 3; i++) {
        *(float2*)&gv[2*i] = *(const float2*)(g + lane*6 + 2*i);
        *(float2*)&bv[2*i] = *(const float2*)(b + lane*6 + 2*i);
    }
    uint32_t* orow = (uint32_t*)(out + (size_t)token * C + lane * 6);
#pragma unroll
    for (int i = 0; i < 3; i++) {
        float a0 = (v[2*i]   - mean) * rstd * gv[2*i]   + bv[2*i];
        float a1 = (v[2*i+1] - mean) * rstd * gv[2*i+1] + bv[2*i+1];
        orow[i] = bf2(a0, a1);
    }
}

// ---------------- bf16 tensor-core GEMM: cp.async 3-stage + ldmatrix --------
// OUT[M,N] = epi( A[M,K] @ Wp^T + bias ), Wp packed [N][K] bf16.
// BM=128, BN=96, BK=32, 256 threads = 8 warps 4(m)x2(n), warp tile 32x48.
// smem per stage: A 128 rows + B 96 rows, each row 32 bf16 = 64B data
// padded to 80B (5x16B chunks) -> 80*r mod 128 distinct for r in 0..7
// => conflict-free ldmatrix without swizzle.

#define STAGES      3
#define A_STAGE_B   (128*80)                 // 10240
#define B_STAGE_B   (96*80)                  // 7680
#define STAGE_B     (A_STAGE_B + B_STAGE_B)  // 17920
#define GSMEM_TOTAL (STAGES * STAGE_B)       // 53760

__device__ __forceinline__ void mma_bf16(float* d, const uint32_t* a,
                                         uint32_t b0, uint32_t b1) {
    asm volatile(
        "mma.sync.aligned.m16n8k16.row.col.f32.bf16.bf16.f32 "
        "{%0,%1,%2,%3},{%4,%5,%6,%7},{%8,%9},{%0,%1,%2,%3};"
        : "+f"(d[0]), "+f"(d[1]), "+f"(d[2]), "+f"(d[3])
        : "r"(a[0]), "r"(a[1]), "r"(a[2]), "r"(a[3]), "r"(b0), "r"(b1));
}

__device__ __forceinline__ void ldsm4(uint32_t& r0, uint32_t& r1,
                                      uint32_t& r2, uint32_t& r3,
                                      uint32_t addr) {
    asm volatile(
        "ldmatrix.sync.aligned.m8n8.x4.shared.b16 {%0,%1,%2,%3}, [%4];"
        : "=r"(r0), "=r"(r1), "=r"(r2), "=r"(r3) : "r"(addr));
}

__device__ __forceinline__ void cp16(uint32_t dst, const void* src) {
    asm volatile("cp.async.cg.shared.global [%0], [%1], 16;"
                 :: "r"(dst), "l"(src));
}
#define CP_COMMIT()  asm volatile("cp.async.commit_group;")
#define CP_WAIT1()   asm volatile("cp.async.wait_group 1;")

__device__ __forceinline__ uint32_t smem_u32(const void* p) {
    uint32_t a;
    asm("{ .reg .u64 t; cvta.to.shared.u64 t, %1; cvt.u32.u64 %0, t; }"
        : "=r"(a) : "l"(p));
    return a;
}

__device__ __forceinline__ void
issue_stage(uint32_t sbase, int stage, const bf16* __restrict__ A,
            const bf16* __restrict__ Wp, int K, int m0, int n0,
            int kt, int tid) {
    uint32_t ab = sbase + stage * STAGE_B;
    uint32_t bb = ab + A_STAGE_B;
    // A: 512 16B-chunks, 2 per thread
#pragma unroll
    for (int r = 0; r < 2; r++) {
        int i = tid + r * 256;
        cp16(ab + (((i >> 2) * 5 + (i & 3)) << 4),
             A + (size_t)(m0 + (i >> 2)) * K + kt * 32 + (i & 3) * 8);
    }
    // B: 384 chunks: all threads one, first 128 threads a second
    cp16(bb + (((tid >> 2) * 5 + (tid & 3)) << 4),
         Wp + (size_t)(n0 + (tid >> 2)) * K + kt * 32 + (tid & 3) * 8);
    if (tid < 128) {
        int i = tid + 256;
        cp16(bb + (((i >> 2) * 5 + (i & 3)) << 4),
             Wp + (size_t)(n0 + (i >> 2)) * K + kt * 32 + (i & 3) * 8);
    }
}

template<int EPI, bool OUT_BF16>
__device__ __forceinline__ void
gemm_body(char* sm, const bf16* __restrict__ A, const bf16* __restrict__ Wp,
          const float* __restrict__ bias, const float* __restrict__ res,
          void* __restrict__ outv, int N, int K, int n0, int m0) {
    const int tid  = threadIdx.x;
    const int wid  = tid >> 5, lane = tid & 31;
    const int wm   = wid >> 1, wn = wid & 1;
    const int gid  = lane >> 2, tig = lane & 3;

    uint32_t sbase = smem_u32(sm);

    // per-lane ldmatrix offsets within a stage (s-half adds 32B)
    uint32_t a_off[2], b_off[3];
#pragma unroll
    for (int mt = 0; mt < 2; mt++)
        a_off[mt] = ((wm*32 + mt*16 + (lane & 15)) * 5 + (lane >> 4)) * 16;
#pragma unroll
    for (int p = 0; p < 3; p++)
        b_off[p] = A_STAGE_B +
            ((wn*48 + p*16 + ((lane >> 4) & 1)*8 + (lane & 7)) * 5 +
             ((lane >> 3) & 1)) * 16;

    float acc[2][6][4];
#pragma unroll
    for (int mt = 0; mt < 2; mt++)
#pragma unroll
        for (int nt = 0; nt < 6; nt++)
#pragma unroll
            for (int r = 0; r < 4; r++) acc[mt][nt][r] = 0.f;

    const int nk = K / 32;

    // prologue: stages 0,1 in flight
    issue_stage(sbase, 0, A, Wp, K, m0, n0, 0, tid);
    CP_COMMIT();
    issue_stage(sbase, 1, A, Wp, K, m0, n0, 1, tid);
    CP_COMMIT();

    int stage = 0;
    for (int kt = 0; kt < nk; kt++) {
        CP_WAIT1();
        __syncthreads();

        uint32_t sb = sbase + stage * STAGE_B;
#pragma unroll
        for (int s = 0; s < 2; s++) {
            uint32_t af[2][4];
#pragma unroll
            for (int mt = 0; mt < 2; mt++)
                ldsm4(af[mt][0], af[mt][1], af[mt][2], af[mt][3],
                      sb + a_off[mt] + s*32);
            uint32_t bf[3][4];
#pragma unroll
            for (int p = 0; p < 3; p++)
                ldsm4(bf[p][0], bf[p][1], bf[p][2], bf[p][3],
                      sb + b_off[p] + s*32);
#pragma unroll
            for (int nt = 0; nt < 6; nt++) {
                uint32_t b0 = bf[nt >> 1][(nt & 1)*2];
                uint32_t b1 = bf[nt >> 1][(nt & 1)*2 + 1];
#pragma unroll
                for (int mt = 0; mt < 2; mt++)
                    mma_bf16(acc[mt][nt], af[mt], b0, b1);
            }
        }

        int nx = kt + STAGES - 1;
        if (nx < nk) {
            int ns = stage + STAGES - 1;
            if (ns >= STAGES) ns -= STAGES;
            issue_stage(sbase, ns, A, Wp, K, m0, n0, nx, tid);
        }
        CP_COMMIT();
        if (++stage == STAGES) stage = 0;
    }

    // epilogue
#pragma unroll
    for (int nt = 0; nt < 6; nt++) {
        int cb = n0 + wn*48 + nt*8 + 2*tig;
        float b0 = bias[cb], b1 = bias[cb + 1];
#pragma unroll
        for (int mt = 0; mt < 2; mt++) {
            int r0 = m0 + wm*32 + mt*16 + gid;
#pragma unroll
            for (int hh = 0; hh < 2; hh++) {
                int r = r0 + hh*8;
                float v0 = acc[mt][nt][hh*2 + 0] + b0;
                float v1 = acc[mt][nt][hh*2 + 1] + b1;
                if (EPI == 1) { v0 = v0 * normcdff(v0); v1 = v1 * normcdff(v1); }
                if (EPI == 2) {
                    const float* rr = res + (size_t)r * N + cb;
                    v0 += rr[0]; v1 += rr[1];
                }
                if (OUT_BF16)
                    *(uint32_t*)((bf16*)outv + (size_t)r * N + cb) = bf2(v0, v1);
                else
                    *(float2*)((float*)outv + (size_t)r * N + cb) =
                        make_float2(v0, v1);
            }
        }
    }
}

template<int EPI, bool OUT_BF16>
__global__ void __launch_bounds__(256, 2)
gemm_k(const bf16* __restrict__ A, const bf16* __restrict__ Wp,
       const float* __restrict__ bias, const float* __restrict__ res,
       void* __restrict__ out, int N, int K) {
    extern __shared__ char sm[];
    gemm_body<EPI, OUT_BF16>(sm, A, Wp, bias, res, out, N, K,
                             blockIdx.x * 96, blockIdx.y * 128);
}

// fused q + kv projection (shares the A read of xn)
__global__ void __launch_bounds__(256, 2)
gemm_qkv(const bf16* __restrict__ A,
         const bf16* __restrict__ Wq,  const float* __restrict__ bq,
         bf16* __restrict__ qout,
         const bf16* __restrict__ Wkv, const float* __restrict__ bkv,
         bf16* __restrict__ kvout) {
    extern __shared__ char sm[];
    if (blockIdx.x < 2)
        gemm_body<0, true>(sm, A, Wq, bq, nullptr, qout, 192, 192,
                           blockIdx.x * 96, blockIdx.y * 128);
    else
        gemm_body<0, true>(sm, A, Wkv, bkv, nullptr, kvout, 96, 192,
                           0, blockIdx.y * 128);
}

// ---------------- fused window attention (bf16 I/O) -------------------------
__global__ void __launch_bounds__(384)
attn_kernel(const bf16* __restrict__ q, const bf16* __restrict__ kv,
            const float* __restrict__ table, bf16* __restrict__ aw) {
    __shared__ float ks[16*192];
    __shared__ float vs[16*192];
    __shared__ float tb[49*HEADS];

    int w  = blockIdx.x;
    int bb = w >> 10;
    int wi = w & 1023;
    int wy = wi >> 5, wx = wi & 31;
    size_t base = (size_t)bb * HW + (size_t)(wy*8) * IMW + wx*8;
    int tid = threadIdx.x;

    for (int e = tid; e < 49*HEADS; e += 384) tb[e] = table[e];

    for (int e = tid; e < 64*48; e += 384) {
        int s  = e / 48, cc = e - s*48;
        int r  = s >> 3, c = s & 7;
        int p  = (r >> 1) * 4 + (c >> 1);
        int f  = (r & 1) * 96 + (c & 1) * 48 + cc;
        const bf16* src = kv + (base + (size_t)r * IMW + c) * (C/2);
        ks[p*192 + f] = __bfloat162float(src[cc]);
        vs[p*192 + f] = __bfloat162float(src[48 + cc]);
    }
    __syncthreads();

    int h  = tid / 64;
    int qt = tid & 63;
    int r  = qt >> 3, c = qt & 7;
    int ph = r >> 1, pw = c >> 1;

    size_t tok = base + (size_t)r * IMW + c;
    const uint4* q4 = (const uint4*)(q + tok * C + h*HD);
    float qr[HD];
#pragma unroll
    for (int i = 0; i < 4; i++) {
        uint4 t = q4[i];
        uint32_t u[4] = {t.x, t.y, t.z, t.w};
#pragma unroll
        for (int j = 0; j < 4; j++) {
            float2 f2 = __bfloat1622float2(*(bf162*)&u[j]);
            qr[i*8 + 2*j]     = f2.x * SCALE_Q;
            qr[i*8 + 2*j + 1] = f2.y * SCALE_Q;
        }
    }

    float s[16], m = -1e30f;
#pragma unroll
    for (int kt = 0; kt < 16; kt++) {
        int kh = kt >> 2, kw = kt & 3;
        float acc = tb[((ph - kh + 3) * 7 + (pw - kw + 3)) * HEADS + h];
        const float* kr = &ks[kt*192 + h*HD];
#pragma unroll
        for (int d = 0; d < HD; d++) acc += qr[d] * kr[d];
        s[kt] = acc;
        m = fmaxf(m, acc);
    }
    float sum = 0.f;
#pragma unroll
    for (int kt = 0; kt < 16; kt++) { s[kt] = __expf(s[kt] - m); sum += s[kt]; }
    float inv = 1.0f / sum;

    float ov[HD];
#pragma unroll
    for (int d = 0; d < HD; d++) {
        float o = 0.f;
#pragma unroll
        for (int kt = 0; kt < 16; kt++) o += s[kt] * vs[kt*192 + h*HD + d];
        ov[d] = o * inv;
    }
    uint4* ow = (uint4*)(aw + tok * C + h*HD);
#pragma unroll
    for (int i = 0; i < 4; i++) {
        uint4 t;
        t.x = bf2(ov[i*8+0], ov[i*8+1]);
        t.y = bf2(ov[i*8+2], ov[i*8+3]);
        t.z = bf2(ov[i*8+4], ov[i*8+5]);
        t.w = bf2(ov[i*8+6], ov[i*8+7]);
        ow[i] = t;
    }
}

// ---------------- depthwise 5x5 conv + gelu + add (bf16 I/O) ----------------
__global__ void __launch_bounds__(256)
dwconv_kernel(const bf16* __restrict__ h1, const float* __restrict__ dwk,
              const float* __restrict__ dwb, bf16* __restrict__ out) {
    constexpr int TS = 16, CCH = 32, TT = TS + 4;
    extern __shared__ float smem[];
    float* tile = smem;
    float* wk   = tile + TT*TT*CCH;
    float* bk   = wk + CCH*25;

    int bz = blockIdx.z;
    int bb = bz / (HIDDEN / CCH);
    int c0 = (bz % (HIDDEN / CCH)) * CCH;
    int x0 = blockIdx.x * TS, y0 = blockIdx.y * TS;
    int tid = threadIdx.x;

    for (int e = tid; e < CCH*25; e += 256) {
        int cc = e / 25, t = e - cc*25;
        wk[cc*25 + t] = dwk[(c0 + cc) * 25 + t];
    }
    if (tid < CCH) bk[tid] = dwb[c0 + tid];

    for (int e = tid; e < TT*TT*(CCH/8); e += 256) {
        int pos = e / (CCH/8);
        int qv  = e - pos*(CCH/8);
        int py = pos / TT, px = pos - py*TT;
        int gy = y0 + py - 2, gx = x0 + px - 2;
        float f[8] = {0,0,0,0,0,0,0,0};
        if (gy >= 0 && gy < IMH && gx >= 0 && gx < IMW) {
            uint4 t = *(const uint4*)(h1 +
                ((size_t)bb*HW + (size_t)gy*IMW + gx)*HIDDEN + c0 + qv*8);
            uint32_t u[4] = {t.x, t.y, t.z, t.w};
#pragma unroll
            for (int j = 0; j < 4; j++) {
                float2 f2 = __bfloat1622float2(*(bf162*)&u[j]);
                f[2*j] = f2.x; f[2*j+1] = f2.y;
            }
        }
        float* dst = &tile[(py*TT + px)*CCH + qv*8];
#pragma unroll
        for (int j = 0; j < 8; j++) dst[j] = f[j];
    }
    __syncthreads();

    int cc = tid & (CCH-1);
    int st = tid >> 5;
    const float* wr = &wk[cc*25];
    float bia = bk[cc];

    for (int it = 0; it < 8; it++) {
        int task = it*8 + st;
        int x  = task & 15;
        int ys = task >> 4;
        float acc[4] = {0.f, 0.f, 0.f, 0.f};
#pragma unroll
        for (int rr = 0; rr < 8; rr++) {
            int py = ys*4 + rr;
            float v[5];
#pragma unroll
            for (int dx = 0; dx < 5; dx++)
                v[dx] = tile[(py*TT + x + dx)*CCH + cc];
#pragma unroll
            for (int j = 0; j < 4; j++) {
                int ky = rr - j;
                if (ky >= 0 && ky < 5) {
#pragma unroll
                    for (int dx = 0; dx < 5; dx++)
                        acc[j] += v[dx] * wr[ky*5 + dx];
                }
            }
        }
#pragma unroll
        for (int j = 0; j < 4; j++) {
            int y = ys*4 + j;
            float rj = tile[((y+2)*TT + (x+2))*CCH + cc];
            float gv = acc[j] + bia;
            gv = gv * normcdff(gv);
            size_t o = ((size_t)bb*HW + (size_t)(y0+y)*IMW + (x0+x))*HIDDEN
                     + c0 + cc;
            out[o] = __float2bfloat16(rj + gv);
        }
    }
}

// ---------------- launch ----------------------------------------------------
extern "C" void kernel_launch(void* const* d_in, const int* in_sizes, int n_in,
                              void* d_out, int out_size) {
    const float* x     = (const float*)d_in[0];
    const float* g1    = (const float*)d_in[1];
    const float* be1   = (const float*)d_in[2];
    const float* wq    = (const float*)d_in[3];
    const float* bq    = (const float*)d_in[4];
    const float* wkv   = (const float*)d_in[5];
    const float* bkv   = (const float*)d_in[6];
    const float* table = (const float*)d_in[7];
    const float* wproj = (const float*)d_in[8];
    const float* bproj = (const float*)d_in[9];
    const float* g2    = (const float*)d_in[10];
    const float* be2   = (const float*)d_in[11];
    const float* w1f   = (const float*)d_in[12];
    const float* b1f   = (const float*)d_in[13];
    const float* dwk   = (const float*)d_in[14];
    const float* dwb   = (const float*)d_in[15];
    const float* w2f   = (const float*)d_in[16];
    const float* b2f   = (const float*)d_in[17];
    float* out = (float*)d_out;

    void *pxn, *pq, *pkv, *paw, *pxmid, *ph1, *ph2, *pwp;
    cudaGetSymbolAddress(&pxn,   g_xn);
    cudaGetSymbolAddress(&pq,    g_q);
    cudaGetSymbolAddress(&pkv,   g_kv);
    cudaGetSymbolAddress(&paw,   g_aw);
    cudaGetSymbolAddress(&pxmid, g_xmid);
    cudaGetSymbolAddress(&ph1,   g_h1);
    cudaGetSymbolAddress(&ph2,   g_h2);
    cudaGetSymbolAddress(&pwp,   g_wp);
    bf16*  xn   = (bf16*)pxn;
    bf16*  qb   = (bf16*)pq;
    bf16*  kvb  = (bf16*)pkv;
    bf16*  awb  = (bf16*)paw;
    float* xmid = (float*)pxmid;
    bf16*  h1   = (bf16*)ph1;
    bf16*  h2   = (bf16*)ph2;
    bf16*  wp   = (bf16*)pwp;

    const int CSMEM = (20*20*32 + 32*25 + 32) * 4;
    cudaFuncSetAttribute(dwconv_kernel,
        cudaFuncAttributeMaxDynamicSharedMemorySize, CSMEM);
    cudaFuncSetAttribute(gemm_k<2, false>,
        cudaFuncAttributeMaxDynamicSharedMemorySize, GSMEM_TOTAL);
    cudaFuncSetAttribute(gemm_k<1, true>,
        cudaFuncAttributeMaxDynamicSharedMemorySize, GSMEM_TOTAL);
    cudaFuncSetAttribute(gemm_qkv,
        cudaFuncAttributeMaxDynamicSharedMemorySize, GSMEM_TOTAL);

    dim3 lnb(32, 8);
    const int MB = M_TOK / 128;   // 1024 m-blocks

    // 0) pack all weights to bf16 [N][K]
    pack_all<<<(387072 + 255)/256, 256>>>(wq, wkv, wproj, w1f, w2f, wp);

    // 1) LN1 -> xn (bf16)
    ln_kernel<<<M_TOK/8, lnb>>>(x, g1, be1, xn);
    // 2+3) fused q & kv projections
    gemm_qkv<<<dim3(3, MB), 256, GSMEM_TOTAL>>>(xn, wp + WP_Q, bq, qb,
                                                wp + WP_KV, bkv, kvb);
    // 4) window attention -> aw (bf16)
    attn_kernel<<<2048, 384>>>(qb, kvb, table, awb);
    // 5) xmid = x + aw @ wproj + bproj (fp32 out)
    gemm_k<2, false><<<dim3(2, MB), 256, GSMEM_TOTAL>>>(
        awb, wp + WP_PROJ, bproj, x, xmid, 192, 192);
    // 6) LN2 -> xn
    ln_kernel<<<M_TOK/8, lnb>>>(xmid, g2, be2, xn);
    // 7) h1 = gelu(xn @ w1f + b1f)
    gemm_k<1, true><<<dim3(8, MB), 256, GSMEM_TOTAL>>>(
        xn, wp + WP_F1, b1f, nullptr, h1, 768, 192);
    // 8) h2 = h1 + gelu(dwconv(h1) + dwb)
    dwconv_kernel<<<dim3(IMW/16, IMH/16, BATCH*(HIDDEN/32)), 256, CSMEM>>>(
        h1, dwk, dwb, h2);
    // 9) out = xmid + h2 @ w2f + b2f (fp32 out, K=768)
    gemm_k<2, false><<<dim3(2, MB), 256, GSMEM_TOTAL>>>(
        h2, wp + WP_F2, b2f, xmid, out, 192, 768);
}